// round 1
// baseline (speedup 1.0000x reference)
#include <cuda_runtime.h>
#include <math.h>

#define Bb 8
#define Cc 512
#define NH 4
#define CH 128
#define LL 1024
#define BH 32
#define ALPHA 0.088388347648318447f   // 1/sqrt(128)

// ---------------- device scratch (allocation-free rule: static globals) ----
__device__ float g_W[(size_t)BH * LL * LL];     // attention scores, 134 MB
__device__ float g_t1[(size_t)Bb * Cc * LL];    // _c
__device__ float g_t2[(size_t)Bb * Cc * LL];    // _e
__device__ float g_x [(size_t)Bb * Cc * LL];    // conv output pre-BN
__device__ float g_stats[2 * Cc];               // mean, invstd

// ============================================================================
// QK: W[t,s] = ALPHA * sum_c Q[c,t] * K[c,s]   (per head; Q,K are [128,1024])
// grid (8, 8, 32), block 256, 128x128 tile, 8x8 micro-tile, k-chunk 8
// ============================================================================
__global__ __launch_bounds__(256, 2)
void gemm_qk(const float* __restrict__ Q, const float* __restrict__ K) {
    const int bh = blockIdx.z;
    const float* Qh = Q + (size_t)bh * CH * LL;
    const float* Kh = K + (size_t)bh * CH * LL;
    float* Wh = g_W + (size_t)bh * LL * LL;

    __shared__ float As[8][128];
    __shared__ float Bs[8][128];

    const int t0 = blockIdx.y * 128;
    const int s0 = blockIdx.x * 128;
    const int tid = threadIdx.x;
    const int tx = tid & 15, ty = tid >> 4;
    const int lr = tid >> 5;            // chunk row 0..7
    const int lc = (tid * 4) & 127;     // chunk col

    float acc[8][8] = {};

    for (int k0 = 0; k0 < CH; k0 += 8) {
        float4 a = *(const float4*)(Qh + (size_t)(k0 + lr) * LL + t0 + lc);
        float4 b = *(const float4*)(Kh + (size_t)(k0 + lr) * LL + s0 + lc);
        *(float4*)&As[lr][lc] = a;
        *(float4*)&Bs[lr][lc] = b;
        __syncthreads();
        #pragma unroll
        for (int kk = 0; kk < 8; kk++) {
            float av[8], bv[8];
            *(float4*)(av)     = *(const float4*)&As[kk][ty * 8];
            *(float4*)(av + 4) = *(const float4*)&As[kk][ty * 8 + 4];
            *(float4*)(bv)     = *(const float4*)&Bs[kk][tx * 8];
            *(float4*)(bv + 4) = *(const float4*)&Bs[kk][tx * 8 + 4];
            #pragma unroll
            for (int i = 0; i < 8; i++)
                #pragma unroll
                for (int j = 0; j < 8; j++)
                    acc[i][j] += av[i] * bv[j];
        }
        __syncthreads();
    }

    #pragma unroll
    for (int i = 0; i < 8; i++) {
        float* row = Wh + (size_t)(t0 + ty * 8 + i) * LL + s0 + tx * 8;
        float4 v0 = make_float4(acc[i][0] * ALPHA, acc[i][1] * ALPHA,
                                acc[i][2] * ALPHA, acc[i][3] * ALPHA);
        float4 v1 = make_float4(acc[i][4] * ALPHA, acc[i][5] * ALPHA,
                                acc[i][6] * ALPHA, acc[i][7] * ALPHA);
        *(float4*)row       = v0;
        *(float4*)(row + 4) = v1;
    }
}

// ============================================================================
// Row softmax over g_W: 32768 rows of 1024. One block per row, 256 threads.
// ============================================================================
__global__ __launch_bounds__(256)
void softmax_rows() {
    float* p = g_W + (size_t)blockIdx.x * LL;
    const int tid = threadIdx.x;

    float4 v = *(const float4*)(p + tid * 4);

    float m = fmaxf(fmaxf(v.x, v.y), fmaxf(v.z, v.w));
    #pragma unroll
    for (int o = 16; o; o >>= 1) m = fmaxf(m, __shfl_xor_sync(~0u, m, o));

    __shared__ float redm[8];
    __shared__ float reds[8];
    if ((tid & 31) == 0) redm[tid >> 5] = m;
    __syncthreads();
    float mx = redm[0];
    #pragma unroll
    for (int w = 1; w < 8; w++) mx = fmaxf(mx, redm[w]);

    v.x = expf(v.x - mx);
    v.y = expf(v.y - mx);
    v.z = expf(v.z - mx);
    v.w = expf(v.w - mx);

    float s = v.x + v.y + v.z + v.w;
    #pragma unroll
    for (int o = 16; o; o >>= 1) s += __shfl_xor_sync(~0u, s, o);
    if ((tid & 31) == 0) reds[tid >> 5] = s;
    __syncthreads();
    float st = 0.f;
    #pragma unroll
    for (int w = 0; w < 8; w++) st += reds[w];

    float inv = 1.0f / st;
    v.x *= inv; v.y *= inv; v.z *= inv; v.w *= inv;
    *(float4*)(p + tid * 4) = v;
}

// ============================================================================
// AV: Out[c,t] = sum_s V[c,s] * W[t,s]   (per head; V [128,1024], W [1024,1024])
// grid (8, 1, 32), block 256, output tile 128(c) x 128(t), k-chunk 8
// ============================================================================
__global__ __launch_bounds__(256, 2)
void gemm_av(const float* __restrict__ V, float* __restrict__ Out) {
    const int bh = blockIdx.z;
    const float* Vh = V   + (size_t)bh * CH * LL;
    const float* Wh = g_W + (size_t)bh * LL * LL;
    float* Oh = Out + (size_t)bh * CH * LL;

    __shared__ float As[8][132];   // As[s][c]  (padded: conflict-free transpose)
    __shared__ float Bs[8][132];   // Bs[s][t]

    const int t0 = blockIdx.x * 128;
    const int tid = threadIdx.x;
    const int tx = tid & 15, ty = tid >> 4;
    const int rr = tid >> 1;            // 0..127
    const int si = (tid & 1) * 4;       // 0 or 4

    float acc[8][8] = {};

    for (int s0 = 0; s0 < LL; s0 += 8) {
        float4 a = *(const float4*)(Vh + (size_t)rr * LL + s0 + si);
        float4 b = *(const float4*)(Wh + (size_t)(t0 + rr) * LL + s0 + si);
        As[si + 0][rr] = a.x; As[si + 1][rr] = a.y;
        As[si + 2][rr] = a.z; As[si + 3][rr] = a.w;
        Bs[si + 0][rr] = b.x; Bs[si + 1][rr] = b.y;
        Bs[si + 2][rr] = b.z; Bs[si + 3][rr] = b.w;
        __syncthreads();
        #pragma unroll
        for (int kk = 0; kk < 8; kk++) {
            float av[8], bv[8];
            *(float4*)(av)     = *(const float4*)&As[kk][ty * 8];
            *(float4*)(av + 4) = *(const float4*)&As[kk][ty * 8 + 4];
            *(float4*)(bv)     = *(const float4*)&Bs[kk][tx * 8];
            *(float4*)(bv + 4) = *(const float4*)&Bs[kk][tx * 8 + 4];
            #pragma unroll
            for (int i = 0; i < 8; i++)
                #pragma unroll
                for (int j = 0; j < 8; j++)
                    acc[i][j] += av[i] * bv[j];
        }
        __syncthreads();
    }

    #pragma unroll
    for (int i = 0; i < 8; i++) {
        float* row = Oh + (size_t)(ty * 8 + i) * LL + t0 + tx * 8;
        *(float4*)row       = *(float4*)&acc[i][0];
        *(float4*)(row + 4) = *(float4*)&acc[i][4];
    }
}

// ============================================================================
// 1x1 conv: X[b,o,l] = sum_c Wc[o,c] * E[b,c,l] + bias[o]
// grid (8, 4, 8), block 256, tile 128(o) x 128(l), k-chunk 8
// ============================================================================
__global__ __launch_bounds__(256, 2)
void gemm_conv(const float* __restrict__ Wc, const float* __restrict__ Ein,
               const float* __restrict__ bias) {
    const int b = blockIdx.z;
    const float* Eb = Ein + (size_t)b * Cc * LL;
    float* Xb = g_x + (size_t)b * Cc * LL;

    __shared__ float As[8][132];   // As[c][o] (transposed)
    __shared__ float Bs[8][132];   // Bs[c][l] (direct)

    const int o0 = blockIdx.y * 128;
    const int l0 = blockIdx.x * 128;
    const int tid = threadIdx.x;
    const int tx = tid & 15, ty = tid >> 4;
    const int rr = tid >> 1, ci = (tid & 1) * 4;   // A loader
    const int lr = tid >> 5, lc = (tid * 4) & 127; // B loader

    float acc[8][8] = {};

    for (int c0 = 0; c0 < Cc; c0 += 8) {
        float4 a = *(const float4*)(Wc + (size_t)(o0 + rr) * Cc + c0 + ci);
        float4 bb = *(const float4*)(Eb + (size_t)(c0 + lr) * LL + l0 + lc);
        As[ci + 0][rr] = a.x; As[ci + 1][rr] = a.y;
        As[ci + 2][rr] = a.z; As[ci + 3][rr] = a.w;
        *(float4*)&Bs[lr][lc] = bb;
        __syncthreads();
        #pragma unroll
        for (int kk = 0; kk < 8; kk++) {
            float av[8], bv[8];
            *(float4*)(av)     = *(const float4*)&As[kk][ty * 8];
            *(float4*)(av + 4) = *(const float4*)&As[kk][ty * 8 + 4];
            *(float4*)(bv)     = *(const float4*)&Bs[kk][tx * 8];
            *(float4*)(bv + 4) = *(const float4*)&Bs[kk][tx * 8 + 4];
            #pragma unroll
            for (int i = 0; i < 8; i++)
                #pragma unroll
                for (int j = 0; j < 8; j++)
                    acc[i][j] += av[i] * bv[j];
        }
        __syncthreads();
    }

    #pragma unroll
    for (int i = 0; i < 8; i++) {
        const int o = o0 + ty * 8 + i;
        const float bo = bias[o];
        float* row = Xb + (size_t)o * LL + l0 + tx * 8;
        float4 v0 = make_float4(acc[i][0] + bo, acc[i][1] + bo,
                                acc[i][2] + bo, acc[i][3] + bo);
        float4 v1 = make_float4(acc[i][4] + bo, acc[i][5] + bo,
                                acc[i][6] + bo, acc[i][7] + bo);
        *(float4*)row       = v0;
        *(float4*)(row + 4) = v1;
    }
}

// ============================================================================
// BN stats: per-channel mean / invstd over (B, L) = 8192 values
// ============================================================================
__global__ __launch_bounds__(256)
void bn_stats() {
    const int o = blockIdx.x;
    float s = 0.f, sq = 0.f;
    for (int idx = threadIdx.x; idx < Bb * LL; idx += 256) {
        const int b = idx >> 10;
        const int l = idx & (LL - 1);
        float x = g_x[((size_t)b * Cc + o) * LL + l];
        s += x; sq += x * x;
    }
    __shared__ float rs[256], rq[256];
    rs[threadIdx.x] = s; rq[threadIdx.x] = sq;
    __syncthreads();
    for (int st = 128; st; st >>= 1) {
        if (threadIdx.x < st) {
            rs[threadIdx.x] += rs[threadIdx.x + st];
            rq[threadIdx.x] += rq[threadIdx.x + st];
        }
        __syncthreads();
    }
    if (threadIdx.x == 0) {
        const float n = (float)(Bb * LL);
        float mean = rs[0] / n;
        float var  = rq[0] / n - mean * mean;
        g_stats[o]      = mean;
        g_stats[Cc + o] = rsqrtf(var + 1e-5f);
    }
}

// ============================================================================
// BN normalize + swish  (elementwise, float4)
// ============================================================================
__global__ __launch_bounds__(256)
void bn_swish(const float* __restrict__ gamma, const float* __restrict__ beta,
              float* __restrict__ out) {
    const size_t i = ((size_t)blockIdx.x * blockDim.x + threadIdx.x) * 4;
    const int o = (int)((i >> 10) & (Cc - 1));
    const float m  = g_stats[o];
    const float is = g_stats[Cc + o];
    const float ga = gamma[o];
    const float be = beta[o];
    float4 x = *(const float4*)(g_x + i);
    float4 y;
    {
        float xn = (x.x - m) * is * ga + be; y.x = xn / (1.f + expf(-xn));
    }
    {
        float xn = (x.y - m) * is * ga + be; y.y = xn / (1.f + expf(-xn));
    }
    {
        float xn = (x.z - m) * is * ga + be; y.z = xn / (1.f + expf(-xn));
    }
    {
        float xn = (x.w - m) * is * ga + be; y.w = xn / (1.f + expf(-xn));
    }
    *(float4*)(out + i) = y;
}

// ============================================================================
// launch
// ============================================================================
extern "C" void kernel_launch(void* const* d_in, const int* in_sizes, int n_in,
                              void* d_out, int out_size) {
    const float* c_in   = (const float*)d_in[0];
    const float* e_in   = (const float*)d_in[1];
    const float* conv_w = (const float*)d_in[2];
    const float* conv_b = (const float*)d_in[3];
    const float* gamma  = (const float*)d_in[4];
    const float* beta   = (const float*)d_in[5];
    float* out = (float*)d_out;

    float *t1 = nullptr, *t2 = nullptr;
    cudaGetSymbolAddress((void**)&t1, g_t1);
    cudaGetSymbolAddress((void**)&t2, g_t2);

    const dim3 gqk(8, 8, BH);
    const dim3 gav(8, 1, BH);

    // N_ITERS loop in reference has no feedback -> compute once.
    // attn1: _c = attn(q=e, k=c, v=c)
    gemm_qk<<<gqk, 256>>>(e_in, c_in);
    softmax_rows<<<BH * LL, 256>>>();
    gemm_av<<<gav, 256>>>(c_in, t1);

    // attn2: _e = attn(q=_c, k=e, v=e)
    gemm_qk<<<gqk, 256>>>(t1, e_in);
    softmax_rows<<<BH * LL, 256>>>();
    gemm_av<<<gav, 256>>>(e_in, t2);

    // proj: 1x1 conv + bias
    gemm_conv<<<dim3(8, 4, 8), 256>>>(conv_w, t2, conv_b);

    // BN (training stats) + swish
    bn_stats<<<Cc, 256>>>();
    bn_swish<<<(Bb * Cc * LL) / (256 * 4), 256>>>(gamma, beta, out);
}

// round 4
// speedup vs baseline: 1.1800x; 1.1800x over previous
#include <cuda_runtime.h>
#include <cstdint>
#include <math.h>

#define Bb 8
#define Cc 512
#define CH 128
#define LL 1024
#define BH 32
#define ALPHA 0.088388347648318447f   // 1/sqrt(128)

// ---------------- device scratch ----------------
__device__ float g_W[(size_t)BH * LL * LL];
__device__ float g_t1[(size_t)Bb * Cc * LL];
__device__ float g_t2[(size_t)Bb * Cc * LL];
__device__ float g_x [(size_t)Bb * Cc * LL];
__device__ float g_stats[2 * Cc];

// ==================== helpers ====================
__device__ __forceinline__ uint32_t smem_u32(const void* p) {
    uint32_t a;
    asm("{ .reg .u64 t; cvta.to.shared.u64 t, %1; cvt.u32.u64 %0, t; }" : "=r"(a) : "l"(p));
    return a;
}
__device__ __forceinline__ float to_tf32(float x) {
    uint32_t o;
    asm("cvt.rna.tf32.f32 %0, %1;" : "=r"(o) : "f"(x));
    return __uint_as_float(o);
}

#define MMA8(c, a, b) asm volatile( \
    "mma.sync.aligned.m16n8k8.row.col.f32.tf32.tf32.f32 " \
    "{%0,%1,%2,%3},{%4,%5,%6,%7},{%8,%9},{%0,%1,%2,%3};" \
    : "+f"((c)[0]), "+f"((c)[1]), "+f"((c)[2]), "+f"((c)[3]) \
    : "r"((a)[0]), "r"((a)[1]), "r"((a)[2]), "r"((a)[3]), \
      "r"((b)[0]), "r"((b)[1]))

#define LDS4(r, addr) asm volatile("ld.shared.v4.b32 {%0,%1,%2,%3}, [%4];" \
    : "=r"((r)[0]), "=r"((r)[1]), "=r"((r)[2]), "=r"((r)[3]) : "r"(addr))
#define LDS2(r, addr) asm volatile("ld.shared.v2.b32 {%0,%1}, [%2];" \
    : "=r"((r)[0]), "=r"((r)[1]) : "r"(addr))

// ---- fragment-layout smem indices (float index within a tile) ----
// A tile 128(m) x 32(k): 32 blocks of 136 floats (8-float pad, 16B-aligned).
// block = (k>>3)*8 + (m>>4); within: lane=(m&7)*4+(k&3), reg=((m>>3)&1)+2*((k>>2)&1)
__device__ __forceinline__ int idxA(int m, int k) {
    return (((k >> 3) * 8 + (m >> 4)) * 136)
         + (((m & 7) * 4 + (k & 3)) << 2) + ((m >> 3) & 1) + (((k >> 2) & 1) << 1);
}
// B tile 32(k) x 128(n): 64 blocks of 66 floats (2-float pad, 8B-aligned).
// block = (k>>3)*16 + (n>>3); within: lane=(n&7)*4+(k&3), reg=(k>>2)&1
__device__ __forceinline__ int idxB(int k, int n) {
    return (((k >> 3) * 16 + (n >> 3)) * 66)
         + (((n & 7) * 4 + (k & 3)) << 1) + ((k >> 2) & 1);
}
#define ASZ 4352          // 32 * 136
#define BSZ 4224          // 64 * 66
#define BUF (2 * ASZ + 2 * BSZ)   // Ah, Al, Bh, Bl (floats)
static constexpr size_t SMEMB = (size_t)(2 * BUF) * 4;   // 137216 B (double buffer)

__device__ __forceinline__ void put_pair(float* base, int idx, int lo_off, float x) {
    float h = to_tf32(x);
    base[idx] = h;
    base[idx + lo_off] = to_tf32(x - h);
}

// one 32-K chunk with 3xTF32: per kstep 8 LDS4 + 8 LDS2 + 48 MMAs
__device__ __forceinline__ void chunk_mma3(uint32_t buf, int wm, int wn, int lane,
                                           float acc[4][4][4]) {
    #pragma unroll
    for (int kt = 0; kt < 4; kt++) {
        uint32_t ah[4][4], al[4][4], bh[4][2], bl[4][2];
        #pragma unroll
        for (int i = 0; i < 4; i++) {
            uint32_t ad = buf + (uint32_t)(((kt * 8 + wm * 4 + i) * 136 + (lane << 2)) * 4);
            LDS4(ah[i], ad);
            LDS4(al[i], ad + ASZ * 4);
        }
        #pragma unroll
        for (int j = 0; j < 4; j++) {
            uint32_t ad = buf + (uint32_t)((2 * ASZ + (kt * 16 + wn * 4 + j) * 66 + (lane << 1)) * 4);
            LDS2(bh[j], ad);
            LDS2(bl[j], ad + BSZ * 4);
        }
        #pragma unroll
        for (int i = 0; i < 4; i++)
            #pragma unroll
            for (int j = 0; j < 4; j++) {
                MMA8(acc[i][j], al[i], bh[j]);
                MMA8(acc[i][j], ah[i], bl[j]);
                MMA8(acc[i][j], ah[i], bh[j]);
            }
    }
}

// ============================================================================
// QK: W[t,s] = ALPHA * sum_c Q[c,t] K[c,s].  M=t, N=s, K=c (4 chunks)
// ============================================================================
__global__ __launch_bounds__(256, 1)
void qk_tc(const float* __restrict__ Qm, const float* __restrict__ Km) {
    extern __shared__ float sm[];
    const int tid = threadIdx.x, w = tid >> 5, lane = tid & 31;
    const int wm = w >> 2, wn = w & 3;
    const int bh = blockIdx.z, t0 = blockIdx.y * 128, s0 = blockIdx.x * 128;
    const float* Qh = Qm + (size_t)bh * CH * LL;
    const float* Kh = Km + (size_t)bh * CH * LL;
    float* Wh = g_W + (size_t)bh * LL * LL;

    const uint32_t su = smem_u32(sm);
    float acc[4][4][4] = {};
    float rA[16], rB[16];
    const int mA = w * 16 + (lane & 15);
    const int kof = lane >> 4;

    #pragma unroll
    for (int it = 0; it < 16; it++) {
        int k = it * 2 + kof;
        rA[it] = Qh[(size_t)k * LL + t0 + mA];
        rB[it] = Kh[(size_t)k * LL + s0 + mA];
    }
    #pragma unroll
    for (int it = 0; it < 16; it++) {
        int k = it * 2 + kof;
        put_pair(sm, idxA(mA, k), ASZ, rA[it]);
        put_pair(sm + 2 * ASZ, idxB(k, mA), BSZ, rB[it]);
    }
    __syncthreads();

    for (int ch = 0; ch < 4; ch++) {
        if (ch + 1 < 4) {
            const int c0 = (ch + 1) * 32;
            #pragma unroll
            for (int it = 0; it < 16; it++) {
                int k = c0 + it * 2 + kof;
                rA[it] = Qh[(size_t)k * LL + t0 + mA];
                rB[it] = Kh[(size_t)k * LL + s0 + mA];
            }
        }
        chunk_mma3(su + (uint32_t)((ch & 1) * BUF * 4), wm, wn, lane, acc);
        if (ch + 1 < 4) {
            float* bb = sm + ((ch + 1) & 1) * BUF;
            #pragma unroll
            for (int it = 0; it < 16; it++) {
                int k = it * 2 + kof;
                put_pair(bb, idxA(mA, k), ASZ, rA[it]);
                put_pair(bb + 2 * ASZ, idxB(k, mA), BSZ, rB[it]);
            }
            __syncthreads();
        }
    }

    const int r = lane >> 2, cb = (lane & 3) * 2;
    #pragma unroll
    for (int i = 0; i < 4; i++) {
        const int row = t0 + wm * 64 + i * 16 + r;
        #pragma unroll
        for (int j = 0; j < 4; j++) {
            const int col = s0 + wn * 32 + j * 8 + cb;
            *(float2*)(Wh + (size_t)row * LL + col) =
                make_float2(acc[i][j][0] * ALPHA, acc[i][j][1] * ALPHA);
            *(float2*)(Wh + (size_t)(row + 8) * LL + col) =
                make_float2(acc[i][j][2] * ALPHA, acc[i][j][3] * ALPHA);
        }
    }
}

// ============================================================================
// AV: Out[c,t] = sum_s W[t,s] V[c,s].  M=c, N=t, K=s (32 chunks)
// ============================================================================
__global__ __launch_bounds__(256, 1)
void av_tc(const float* __restrict__ V, float* __restrict__ Out) {
    extern __shared__ float sm[];
    const int tid = threadIdx.x, w = tid >> 5, lane = tid & 31;
    const int wm = w >> 2, wn = w & 3;
    const int bh = blockIdx.z, t0 = blockIdx.x * 128;
    const float* Vh = V + (size_t)bh * CH * LL;
    const float* Wh = g_W + (size_t)bh * LL * LL;
    float* Oh = Out + (size_t)bh * CH * LL;

    const uint32_t su = smem_u32(sm);
    float acc[4][4][4] = {};
    float rA[16], rB[16];

    #pragma unroll
    for (int it = 0; it < 16; it++) {
        rA[it] = Vh[(size_t)(it * 8 + w) * LL + lane];
        rB[it] = Wh[(size_t)(t0 + it * 8 + w) * LL + lane];
    }
    #pragma unroll
    for (int it = 0; it < 16; it++) {
        put_pair(sm, idxA(it * 8 + w, lane), ASZ, rA[it]);
        put_pair(sm + 2 * ASZ, idxB(lane, it * 8 + w), BSZ, rB[it]);
    }
    __syncthreads();

    for (int ch = 0; ch < 32; ch++) {
        if (ch + 1 < 32) {
            const int s0 = (ch + 1) * 32;
            #pragma unroll
            for (int it = 0; it < 16; it++) {
                rA[it] = Vh[(size_t)(it * 8 + w) * LL + s0 + lane];
                rB[it] = Wh[(size_t)(t0 + it * 8 + w) * LL + s0 + lane];
            }
        }
        chunk_mma3(su + (uint32_t)((ch & 1) * BUF * 4), wm, wn, lane, acc);
        if (ch + 1 < 32) {
            float* bb = sm + ((ch + 1) & 1) * BUF;
            #pragma unroll
            for (int it = 0; it < 16; it++) {
                put_pair(bb, idxA(it * 8 + w, lane), ASZ, rA[it]);
                put_pair(bb + 2 * ASZ, idxB(lane, it * 8 + w), BSZ, rB[it]);
            }
            __syncthreads();
        }
    }

    const int r = lane >> 2, cb = (lane & 3) * 2;
    #pragma unroll
    for (int i = 0; i < 4; i++) {
        const int row = wm * 64 + i * 16 + r;
        #pragma unroll
        for (int j = 0; j < 4; j++) {
            const int col = t0 + wn * 32 + j * 8 + cb;
            *(float2*)(Oh + (size_t)row * LL + col) = make_float2(acc[i][j][0], acc[i][j][1]);
            *(float2*)(Oh + (size_t)(row + 8) * LL + col) = make_float2(acc[i][j][2], acc[i][j][3]);
        }
    }
}

// ============================================================================
// conv 1x1: X[o,l] = sum_c Wc[o,c] E[c,l] + bias[o].  M=o, N=l, K=c (16 chunks)
// ============================================================================
__global__ __launch_bounds__(256, 1)
void conv_tc(const float* __restrict__ Wc, const float* __restrict__ Ein,
             const float* __restrict__ bias) {
    extern __shared__ float sm[];
    const int tid = threadIdx.x, w = tid >> 5, lane = tid & 31;
    const int wm = w >> 2, wn = w & 3;
    const int b = blockIdx.z, o0 = blockIdx.y * 128, l0 = blockIdx.x * 128;
    const float* Eb = Ein + (size_t)b * Cc * LL;
    float* Xb = g_x + (size_t)b * Cc * LL;

    const uint32_t su = smem_u32(sm);
    float acc[4][4][4] = {};
    float rA[16], rB[16];
    const int nB = w * 16 + (lane & 15);
    const int kof = lane >> 4;

    #pragma unroll
    for (int it = 0; it < 16; it++) {
        rA[it] = Wc[(size_t)(o0 + it * 8 + w) * Cc + lane];
        rB[it] = Eb[(size_t)(it * 2 + kof) * LL + l0 + nB];
    }
    #pragma unroll
    for (int it = 0; it < 16; it++) {
        put_pair(sm, idxA(it * 8 + w, lane), ASZ, rA[it]);
        put_pair(sm + 2 * ASZ, idxB(it * 2 + kof, nB), BSZ, rB[it]);
    }
    __syncthreads();

    for (int ch = 0; ch < 16; ch++) {
        if (ch + 1 < 16) {
            const int c0 = (ch + 1) * 32;
            #pragma unroll
            for (int it = 0; it < 16; it++) {
                rA[it] = Wc[(size_t)(o0 + it * 8 + w) * Cc + c0 + lane];
                rB[it] = Eb[(size_t)(c0 + it * 2 + kof) * LL + l0 + nB];
            }
        }
        chunk_mma3(su + (uint32_t)((ch & 1) * BUF * 4), wm, wn, lane, acc);
        if (ch + 1 < 16) {
            float* bb = sm + ((ch + 1) & 1) * BUF;
            #pragma unroll
            for (int it = 0; it < 16; it++) {
                put_pair(bb, idxA(it * 8 + w, lane), ASZ, rA[it]);
                put_pair(bb + 2 * ASZ, idxB(it * 2 + kof, nB), BSZ, rB[it]);
            }
            __syncthreads();
        }
    }

    const int r = lane >> 2, cb = (lane & 3) * 2;
    #pragma unroll
    for (int i = 0; i < 4; i++) {
        const int o = o0 + wm * 64 + i * 16 + r;
        const float b0 = bias[o], b1 = bias[o + 8];
        #pragma unroll
        for (int j = 0; j < 4; j++) {
            const int col = l0 + wn * 32 + j * 8 + cb;
            *(float2*)(Xb + (size_t)o * LL + col) =
                make_float2(acc[i][j][0] + b0, acc[i][j][1] + b0);
            *(float2*)(Xb + (size_t)(o + 8) * LL + col) =
                make_float2(acc[i][j][2] + b1, acc[i][j][3] + b1);
        }
    }
}

// ============================================================================
// Row softmax (fp32 output; AV splits at fill)
// ============================================================================
__global__ __launch_bounds__(256)
void softmax_rows() {
    float* p = g_W + (size_t)blockIdx.x * LL;
    const int tid = threadIdx.x;
    float4 v = *(const float4*)(p + tid * 4);

    float m = fmaxf(fmaxf(v.x, v.y), fmaxf(v.z, v.w));
    #pragma unroll
    for (int o = 16; o; o >>= 1) m = fmaxf(m, __shfl_xor_sync(~0u, m, o));
    __shared__ float redm[8], reds[8];
    if ((tid & 31) == 0) redm[tid >> 5] = m;
    __syncthreads();
    float mx = redm[0];
    #pragma unroll
    for (int w = 1; w < 8; w++) mx = fmaxf(mx, redm[w]);

    v.x = expf(v.x - mx); v.y = expf(v.y - mx);
    v.z = expf(v.z - mx); v.w = expf(v.w - mx);
    float s = v.x + v.y + v.z + v.w;
    #pragma unroll
    for (int o = 16; o; o >>= 1) s += __shfl_xor_sync(~0u, s, o);
    if ((tid & 31) == 0) reds[tid >> 5] = s;
    __syncthreads();
    float st = 0.f;
    #pragma unroll
    for (int w = 0; w < 8; w++) st += reds[w];

    float inv = 1.0f / st;
    v.x *= inv; v.y *= inv; v.z *= inv; v.w *= inv;
    *(float4*)(p + tid * 4) = v;
}

// ============================================================================
// BN stats + normalize + swish
// ============================================================================
__global__ __launch_bounds__(256)
void bn_stats() {
    const int o = blockIdx.x;
    float s = 0.f, sq = 0.f;
    for (int idx = threadIdx.x; idx < Bb * LL; idx += 256) {
        const int b = idx >> 10, l = idx & (LL - 1);
        float x = g_x[((size_t)b * Cc + o) * LL + l];
        s += x; sq += x * x;
    }
    __shared__ float rs[256], rq[256];
    rs[threadIdx.x] = s; rq[threadIdx.x] = sq;
    __syncthreads();
    for (int st = 128; st; st >>= 1) {
        if (threadIdx.x < st) {
            rs[threadIdx.x] += rs[threadIdx.x + st];
            rq[threadIdx.x] += rq[threadIdx.x + st];
        }
        __syncthreads();
    }
    if (threadIdx.x == 0) {
        const float n = (float)(Bb * LL);
        float mean = rs[0] / n;
        float var  = rq[0] / n - mean * mean;
        g_stats[o] = mean;
        g_stats[Cc + o] = rsqrtf(var + 1e-5f);
    }
}

__global__ __launch_bounds__(256)
void bn_swish(const float* __restrict__ gamma, const float* __restrict__ beta,
              float* __restrict__ out) {
    const size_t i = ((size_t)blockIdx.x * blockDim.x + threadIdx.x) * 4;
    const int o = (int)((i >> 10) & (Cc - 1));
    const float m = g_stats[o], is = g_stats[Cc + o];
    const float ga = gamma[o], be = beta[o];
    float4 x = *(const float4*)(g_x + i);
    float4 y;
    { float xn = (x.x - m) * is * ga + be; y.x = xn / (1.f + expf(-xn)); }
    { float xn = (x.y - m) * is * ga + be; y.y = xn / (1.f + expf(-xn)); }
    { float xn = (x.z - m) * is * ga + be; y.z = xn / (1.f + expf(-xn)); }
    { float xn = (x.w - m) * is * ga + be; y.w = xn / (1.f + expf(-xn)); }
    *(float4*)(out + i) = y;
}

// ============================================================================
// launch
// ============================================================================
extern "C" void kernel_launch(void* const* d_in, const int* in_sizes, int n_in,
                              void* d_out, int out_size) {
    const float* c_in   = (const float*)d_in[0];
    const float* e_in   = (const float*)d_in[1];
    const float* conv_w = (const float*)d_in[2];
    const float* conv_b = (const float*)d_in[3];
    const float* gamma  = (const float*)d_in[4];
    const float* beta   = (const float*)d_in[5];
    float* out = (float*)d_out;

    float *t1 = nullptr, *t2 = nullptr;
    cudaGetSymbolAddress((void**)&t1, g_t1);
    cudaGetSymbolAddress((void**)&t2, g_t2);

    cudaFuncSetAttribute(qk_tc,   cudaFuncAttributeMaxDynamicSharedMemorySize, (int)SMEMB);
    cudaFuncSetAttribute(av_tc,   cudaFuncAttributeMaxDynamicSharedMemorySize, (int)SMEMB);
    cudaFuncSetAttribute(conv_tc, cudaFuncAttributeMaxDynamicSharedMemorySize, (int)SMEMB);

    // attn1: _c = attn(q=e, k=c, v=c)
    qk_tc<<<dim3(8, 8, BH), 256, SMEMB>>>(e_in, c_in);
    softmax_rows<<<BH * LL, 256>>>();
    av_tc<<<dim3(8, 1, BH), 256, SMEMB>>>(c_in, t1);

    // attn2: _e = attn(q=_c, k=e, v=e)
    qk_tc<<<dim3(8, 8, BH), 256, SMEMB>>>(t1, e_in);
    softmax_rows<<<BH * LL, 256>>>();
    av_tc<<<dim3(8, 1, BH), 256, SMEMB>>>(e_in, t2);

    // proj: 1x1 conv + bias, then BN + swish
    conv_tc<<<dim3(8, 4, 8), 256, SMEMB>>>(conv_w, t2, conv_b);
    bn_stats<<<Cc, 256>>>();
    bn_swish<<<(Bb * Cc * LL) / (256 * 4), 256>>>(gamma, beta, out);
}

// round 5
// speedup vs baseline: 1.2575x; 1.0657x over previous
#include <cuda_runtime.h>
#include <cstdint>
#include <math.h>

#define Bb 8
#define Cc 512
#define CH 128
#define LL 1024
#define BH 32
#define ALPHA 0.088388347648318447f   // 1/sqrt(128)

// ---------------- device scratch ----------------
__device__ float g_W[(size_t)BH * LL * LL];
__device__ float g_t1[(size_t)Bb * Cc * LL];
__device__ float g_t2[(size_t)Bb * Cc * LL];
__device__ float g_x [(size_t)Bb * Cc * LL];
__device__ float g_stats[2 * Cc];

// ==================== helpers ====================
__device__ __forceinline__ uint32_t smem_u32(const void* p) {
    uint32_t a;
    asm("{ .reg .u64 t; cvta.to.shared.u64 t, %1; cvt.u32.u64 %0, t; }" : "=r"(a) : "l"(p));
    return a;
}
__device__ __forceinline__ float to_tf32(float x) {
    uint32_t o;
    asm("cvt.rna.tf32.f32 %0, %1;" : "=r"(o) : "f"(x));
    return __uint_as_float(o);
}

#define MMA8(c, a, b) asm volatile( \
    "mma.sync.aligned.m16n8k8.row.col.f32.tf32.tf32.f32 " \
    "{%0,%1,%2,%3},{%4,%5,%6,%7},{%8,%9},{%0,%1,%2,%3};" \
    : "+f"((c)[0]), "+f"((c)[1]), "+f"((c)[2]), "+f"((c)[3]) \
    : "r"((a)[0]), "r"((a)[1]), "r"((a)[2]), "r"((a)[3]), \
      "r"((b)[0]), "r"((b)[1]))

#define LDS4(r, addr) asm volatile("ld.shared.v4.b32 {%0,%1,%2,%3}, [%4];" \
    : "=r"((r)[0]), "=r"((r)[1]), "=r"((r)[2]), "=r"((r)[3]) : "r"(addr))
#define LDS2(r, addr) asm volatile("ld.shared.v2.b32 {%0,%1}, [%2];" \
    : "=r"((r)[0]), "=r"((r)[1]) : "r"(addr))

// ---- fragment-layout smem indices (float index within a tile, raw fp32) ----
// A tile 128(m) x 32(k): 32 blocks of 136 floats (8-float pad, 16B-aligned).
__device__ __forceinline__ int idxA(int m, int k) {
    return (((k >> 3) * 8 + (m >> 4)) * 136)
         + (((m & 7) * 4 + (k & 3)) << 2) + ((m >> 3) & 1) + (((k >> 2) & 1) << 1);
}
// B tile 32(k) x 128(n): 64 blocks of 66 floats (2-float pad, 8B-aligned).
__device__ __forceinline__ int idxB(int k, int n) {
    return (((k >> 3) * 16 + (n >> 3)) * 66)
         + (((n & 7) * 4 + (k & 3)) << 1) + ((k >> 2) & 1);
}
#define ASZ 4352          // 32 * 136 floats
#define BSZ 4224          // 64 * 66 floats
#define BUF (ASZ + BSZ)   // raw A + raw B per buffer
static constexpr size_t SMEMB = (size_t)(2 * BUF) * 4;   // 68608 B

// one 32-K chunk, 3xTF32 with in-register split (lo terms HW-truncated)
__device__ __forceinline__ void chunk_mma3(uint32_t buf, int wm, int wn, int lane,
                                           float acc[4][4][4]) {
    #pragma unroll
    for (int kt = 0; kt < 4; kt++) {
        uint32_t ar[4][4], br[4][2];
        #pragma unroll
        for (int i = 0; i < 4; i++) {
            uint32_t ad = buf + (uint32_t)(((kt * 8 + wm * 4 + i) * 136 + (lane << 2)) * 4);
            LDS4(ar[i], ad);
        }
        #pragma unroll
        for (int j = 0; j < 4; j++) {
            uint32_t ad = buf + (uint32_t)((ASZ + (kt * 16 + wn * 4 + j) * 66 + (lane << 1)) * 4);
            LDS2(br[j], ad);
        }
        uint32_t ah[4][4], al[4][4], bh[4][2], bl[4][2];
        #pragma unroll
        for (int i = 0; i < 4; i++)
            #pragma unroll
            for (int r = 0; r < 4; r++) {
                float f = __uint_as_float(ar[i][r]);
                float h = to_tf32(f);
                ah[i][r] = __float_as_uint(h);
                al[i][r] = __float_as_uint(f - h);   // HW truncates to tf32
            }
        #pragma unroll
        for (int j = 0; j < 4; j++)
            #pragma unroll
            for (int r = 0; r < 2; r++) {
                float f = __uint_as_float(br[j][r]);
                float h = to_tf32(f);
                bh[j][r] = __float_as_uint(h);
                bl[j][r] = __float_as_uint(f - h);
            }
        #pragma unroll
        for (int i = 0; i < 4; i++)
            #pragma unroll
            for (int j = 0; j < 4; j++) {
                MMA8(acc[i][j], al[i], bh[j]);
                MMA8(acc[i][j], ah[i], bl[j]);
                MMA8(acc[i][j], ah[i], bh[j]);
            }
    }
}

// ============================================================================
// QK: W[t,s] = ALPHA * sum_c Q[c,t] K[c,s].  M=t, N=s, K=c (4 chunks)
// ============================================================================
__global__ __launch_bounds__(256, 1)
void qk_tc(const float* __restrict__ Qm, const float* __restrict__ Km) {
    extern __shared__ float sm[];
    const int tid = threadIdx.x, w = tid >> 5, lane = tid & 31;
    const int wm = w >> 2, wn = w & 3;
    const int bh = blockIdx.z, t0 = blockIdx.y * 128, s0 = blockIdx.x * 128;
    const float* Qh = Qm + (size_t)bh * CH * LL;
    const float* Kh = Km + (size_t)bh * CH * LL;
    float* Wh = g_W + (size_t)bh * LL * LL;

    const uint32_t su = smem_u32(sm);
    float acc[4][4][4] = {};
    float rA[16], rB[16];
    const int mA = w * 16 + (lane & 15);
    const int kof = lane >> 4;

    #pragma unroll
    for (int it = 0; it < 16; it++) {
        int k = it * 2 + kof;
        rA[it] = Qh[(size_t)k * LL + t0 + mA];
        rB[it] = Kh[(size_t)k * LL + s0 + mA];
    }
    #pragma unroll
    for (int it = 0; it < 16; it++) {
        int k = it * 2 + kof;
        sm[idxA(mA, k)] = rA[it];
        sm[ASZ + idxB(k, mA)] = rB[it];
    }
    __syncthreads();

    for (int ch = 0; ch < 4; ch++) {
        if (ch + 1 < 4) {
            const int c0 = (ch + 1) * 32;
            #pragma unroll
            for (int it = 0; it < 16; it++) {
                int k = c0 + it * 2 + kof;
                rA[it] = Qh[(size_t)k * LL + t0 + mA];
                rB[it] = Kh[(size_t)k * LL + s0 + mA];
            }
        }
        chunk_mma3(su + (uint32_t)((ch & 1) * BUF * 4), wm, wn, lane, acc);
        if (ch + 1 < 4) {
            float* bb = sm + ((ch + 1) & 1) * BUF;
            #pragma unroll
            for (int it = 0; it < 16; it++) {
                int k = it * 2 + kof;
                bb[idxA(mA, k)] = rA[it];
                bb[ASZ + idxB(k, mA)] = rB[it];
            }
            __syncthreads();
        }
    }

    const int r = lane >> 2, cb = (lane & 3) * 2;
    #pragma unroll
    for (int i = 0; i < 4; i++) {
        const int row = t0 + wm * 64 + i * 16 + r;
        #pragma unroll
        for (int j = 0; j < 4; j++) {
            const int col = s0 + wn * 32 + j * 8 + cb;
            *(float2*)(Wh + (size_t)row * LL + col) =
                make_float2(acc[i][j][0] * ALPHA, acc[i][j][1] * ALPHA);
            *(float2*)(Wh + (size_t)(row + 8) * LL + col) =
                make_float2(acc[i][j][2] * ALPHA, acc[i][j][3] * ALPHA);
        }
    }
}

// ============================================================================
// AV: Out[c,t] = sum_s W[t,s] V[c,s].  M=c, N=t, K=s (32 chunks)
// ============================================================================
__global__ __launch_bounds__(256, 1)
void av_tc(const float* __restrict__ V, float* __restrict__ Out) {
    extern __shared__ float sm[];
    const int tid = threadIdx.x, w = tid >> 5, lane = tid & 31;
    const int wm = w >> 2, wn = w & 3;
    const int bh = blockIdx.z, t0 = blockIdx.x * 128;
    const float* Vh = V + (size_t)bh * CH * LL;
    const float* Wh = g_W + (size_t)bh * LL * LL;
    float* Oh = Out + (size_t)bh * CH * LL;

    const uint32_t su = smem_u32(sm);
    float acc[4][4][4] = {};
    float rA[16], rB[16];

    #pragma unroll
    for (int it = 0; it < 16; it++) {
        rA[it] = Vh[(size_t)(it * 8 + w) * LL + lane];
        rB[it] = Wh[(size_t)(t0 + it * 8 + w) * LL + lane];
    }
    #pragma unroll
    for (int it = 0; it < 16; it++) {
        sm[idxA(it * 8 + w, lane)] = rA[it];
        sm[ASZ + idxB(lane, it * 8 + w)] = rB[it];
    }
    __syncthreads();

    for (int ch = 0; ch < 32; ch++) {
        if (ch + 1 < 32) {
            const int s0 = (ch + 1) * 32;
            #pragma unroll
            for (int it = 0; it < 16; it++) {
                rA[it] = Vh[(size_t)(it * 8 + w) * LL + s0 + lane];
                rB[it] = Wh[(size_t)(t0 + it * 8 + w) * LL + s0 + lane];
            }
        }
        chunk_mma3(su + (uint32_t)((ch & 1) * BUF * 4), wm, wn, lane, acc);
        if (ch + 1 < 32) {
            float* bb = sm + ((ch + 1) & 1) * BUF;
            #pragma unroll
            for (int it = 0; it < 16; it++) {
                bb[idxA(it * 8 + w, lane)] = rA[it];
                bb[ASZ + idxB(lane, it * 8 + w)] = rB[it];
            }
            __syncthreads();
        }
    }

    const int r = lane >> 2, cb = (lane & 3) * 2;
    #pragma unroll
    for (int i = 0; i < 4; i++) {
        const int row = wm * 64 + i * 16 + r;
        #pragma unroll
        for (int j = 0; j < 4; j++) {
            const int col = t0 + wn * 32 + j * 8 + cb;
            *(float2*)(Oh + (size_t)row * LL + col) = make_float2(acc[i][j][0], acc[i][j][1]);
            *(float2*)(Oh + (size_t)(row + 8) * LL + col) = make_float2(acc[i][j][2], acc[i][j][3]);
        }
    }
}

// ============================================================================
// conv 1x1: X[o,l] = sum_c Wc[o,c] E[c,l] + bias[o].  M=o, N=l, K=c (16 chunks)
// ============================================================================
__global__ __launch_bounds__(256, 1)
void conv_tc(const float* __restrict__ Wc, const float* __restrict__ Ein,
             const float* __restrict__ bias) {
    extern __shared__ float sm[];
    const int tid = threadIdx.x, w = tid >> 5, lane = tid & 31;
    const int wm = w >> 2, wn = w & 3;
    const int b = blockIdx.z, o0 = blockIdx.y * 128, l0 = blockIdx.x * 128;
    const float* Eb = Ein + (size_t)b * Cc * LL;
    float* Xb = g_x + (size_t)b * Cc * LL;

    const uint32_t su = smem_u32(sm);
    float acc[4][4][4] = {};
    float rA[16], rB[16];
    const int nB = w * 16 + (lane & 15);
    const int kof = lane >> 4;

    #pragma unroll
    for (int it = 0; it < 16; it++) {
        rA[it] = Wc[(size_t)(o0 + it * 8 + w) * Cc + lane];
        rB[it] = Eb[(size_t)(it * 2 + kof) * LL + l0 + nB];
    }
    #pragma unroll
    for (int it = 0; it < 16; it++) {
        sm[idxA(it * 8 + w, lane)] = rA[it];
        sm[ASZ + idxB(it * 2 + kof, nB)] = rB[it];
    }
    __syncthreads();

    for (int ch = 0; ch < 16; ch++) {
        if (ch + 1 < 16) {
            const int c0 = (ch + 1) * 32;
            #pragma unroll
            for (int it = 0; it < 16; it++) {
                rA[it] = Wc[(size_t)(o0 + it * 8 + w) * Cc + c0 + lane];
                rB[it] = Eb[(size_t)(c0 + it * 2 + kof) * LL + l0 + nB];
            }
        }
        chunk_mma3(su + (uint32_t)((ch & 1) * BUF * 4), wm, wn, lane, acc);
        if (ch + 1 < 16) {
            float* bb = sm + ((ch + 1) & 1) * BUF;
            #pragma unroll
            for (int it = 0; it < 16; it++) {
                bb[idxA(it * 8 + w, lane)] = rA[it];
                bb[ASZ + idxB(it * 2 + kof, nB)] = rB[it];
            }
            __syncthreads();
        }
    }

    const int r = lane >> 2, cb = (lane & 3) * 2;
    #pragma unroll
    for (int i = 0; i < 4; i++) {
        const int o = o0 + wm * 64 + i * 16 + r;
        const float b0 = bias[o], b1 = bias[o + 8];
        #pragma unroll
        for (int j = 0; j < 4; j++) {
            const int col = l0 + wn * 32 + j * 8 + cb;
            *(float2*)(Xb + (size_t)o * LL + col) =
                make_float2(acc[i][j][0] + b0, acc[i][j][1] + b0);
            *(float2*)(Xb + (size_t)(o + 8) * LL + col) =
                make_float2(acc[i][j][2] + b1, acc[i][j][3] + b1);
        }
    }
}

// ============================================================================
// Row softmax (fp32 output; AV splits at MMA time)
// ============================================================================
__global__ __launch_bounds__(256)
void softmax_rows() {
    float* p = g_W + (size_t)blockIdx.x * LL;
    const int tid = threadIdx.x;
    float4 v = *(const float4*)(p + tid * 4);

    float m = fmaxf(fmaxf(v.x, v.y), fmaxf(v.z, v.w));
    #pragma unroll
    for (int o = 16; o; o >>= 1) m = fmaxf(m, __shfl_xor_sync(~0u, m, o));
    __shared__ float redm[8], reds[8];
    if ((tid & 31) == 0) redm[tid >> 5] = m;
    __syncthreads();
    float mx = redm[0];
    #pragma unroll
    for (int w = 1; w < 8; w++) mx = fmaxf(mx, redm[w]);

    v.x = expf(v.x - mx); v.y = expf(v.y - mx);
    v.z = expf(v.z - mx); v.w = expf(v.w - mx);
    float s = v.x + v.y + v.z + v.w;
    #pragma unroll
    for (int o = 16; o; o >>= 1) s += __shfl_xor_sync(~0u, s, o);
    if ((tid & 31) == 0) reds[tid >> 5] = s;
    __syncthreads();
    float st = 0.f;
    #pragma unroll
    for (int w = 0; w < 8; w++) st += reds[w];

    float inv = 1.0f / st;
    v.x *= inv; v.y *= inv; v.z *= inv; v.w *= inv;
    *(float4*)(p + tid * 4) = v;
}

// ============================================================================
// BN stats + normalize + swish
// ============================================================================
__global__ __launch_bounds__(256)
void bn_stats() {
    const int o = blockIdx.x;
    float s = 0.f, sq = 0.f;
    for (int idx = threadIdx.x; idx < Bb * LL; idx += 256) {
        const int b = idx >> 10, l = idx & (LL - 1);
        float x = g_x[((size_t)b * Cc + o) * LL + l];
        s += x; sq += x * x;
    }
    __shared__ float rs[256], rq[256];
    rs[threadIdx.x] = s; rq[threadIdx.x] = sq;
    __syncthreads();
    for (int st = 128; st; st >>= 1) {
        if (threadIdx.x < st) {
            rs[threadIdx.x] += rs[threadIdx.x + st];
            rq[threadIdx.x] += rq[threadIdx.x + st];
        }
        __syncthreads();
    }
    if (threadIdx.x == 0) {
        const float n = (float)(Bb * LL);
        float mean = rs[0] / n;
        float var  = rq[0] / n - mean * mean;
        g_stats[o] = mean;
        g_stats[Cc + o] = rsqrtf(var + 1e-5f);
    }
}

__global__ __launch_bounds__(256)
void bn_swish(const float* __restrict__ gamma, const float* __restrict__ beta,
              float* __restrict__ out) {
    const size_t i = ((size_t)blockIdx.x * blockDim.x + threadIdx.x) * 4;
    const int o = (int)((i >> 10) & (Cc - 1));
    const float m = g_stats[o], is = g_stats[Cc + o];
    const float ga = gamma[o], be = beta[o];
    float4 x = *(const float4*)(g_x + i);
    float4 y;
    { float xn = (x.x - m) * is * ga + be; y.x = xn / (1.f + expf(-xn)); }
    { float xn = (x.y - m) * is * ga + be; y.y = xn / (1.f + expf(-xn)); }
    { float xn = (x.z - m) * is * ga + be; y.z = xn / (1.f + expf(-xn)); }
    { float xn = (x.w - m) * is * ga + be; y.w = xn / (1.f + expf(-xn)); }
    *(float4*)(out + i) = y;
}

// ============================================================================
// launch
// ============================================================================
extern "C" void kernel_launch(void* const* d_in, const int* in_sizes, int n_in,
                              void* d_out, int out_size) {
    const float* c_in   = (const float*)d_in[0];
    const float* e_in   = (const float*)d_in[1];
    const float* conv_w = (const float*)d_in[2];
    const float* conv_b = (const float*)d_in[3];
    const float* gamma  = (const float*)d_in[4];
    const float* beta   = (const float*)d_in[5];
    float* out = (float*)d_out;

    float *t1 = nullptr, *t2 = nullptr;
    cudaGetSymbolAddress((void**)&t1, g_t1);
    cudaGetSymbolAddress((void**)&t2, g_t2);

    cudaFuncSetAttribute(qk_tc,   cudaFuncAttributeMaxDynamicSharedMemorySize, (int)SMEMB);
    cudaFuncSetAttribute(av_tc,   cudaFuncAttributeMaxDynamicSharedMemorySize, (int)SMEMB);
    cudaFuncSetAttribute(conv_tc, cudaFuncAttributeMaxDynamicSharedMemorySize, (int)SMEMB);

    // attn1: _c = attn(q=e, k=c, v=c)
    qk_tc<<<dim3(8, 8, BH), 256, SMEMB>>>(e_in, c_in);
    softmax_rows<<<BH * LL, 256>>>();
    av_tc<<<dim3(8, 1, BH), 256, SMEMB>>>(c_in, t1);

    // attn2: _e = attn(q=_c, k=e, v=e)
    qk_tc<<<dim3(8, 8, BH), 256, SMEMB>>>(t1, e_in);
    softmax_rows<<<BH * LL, 256>>>();
    av_tc<<<dim3(8, 1, BH), 256, SMEMB>>>(e_in, t2);

    // proj: 1x1 conv + bias, then BN + swish
    conv_tc<<<dim3(8, 4, 8), 256, SMEMB>>>(conv_w, t2, conv_b);
    bn_stats<<<Cc, 256>>>();
    bn_swish<<<(Bb * Cc * LL) / (256 * 4), 256>>>(gamma, beta, out);
}

// round 6
// speedup vs baseline: 1.2602x; 1.0021x over previous
#include <cuda_runtime.h>
#include <cstdint>
#include <math.h>

#define Bb 8
#define Cc 512
#define CH 128
#define LL 1024
#define BH 32
#define ALPHA 0.088388347648318447f   // 1/sqrt(128)

// ---------------- device scratch ----------------
__device__ float g_W[(size_t)BH * LL * LL];
__device__ float g_t1[(size_t)Bb * Cc * LL];
__device__ float g_t2[(size_t)Bb * Cc * LL];
__device__ float g_x [(size_t)Bb * Cc * LL];
__device__ float g_stats[2 * Cc];

// ==================== helpers ====================
__device__ __forceinline__ uint32_t smem_u32(const void* p) {
    uint32_t a;
    asm("{ .reg .u64 t; cvta.to.shared.u64 t, %1; cvt.u32.u64 %0, t; }" : "=r"(a) : "l"(p));
    return a;
}
__device__ __forceinline__ float to_tf32(float x) {
    uint32_t o;
    asm("cvt.rna.tf32.f32 %0, %1;" : "=r"(o) : "f"(x));
    return __uint_as_float(o);
}

#define MMA8(c, a, b) asm volatile( \
    "mma.sync.aligned.m16n8k8.row.col.f32.tf32.tf32.f32 " \
    "{%0,%1,%2,%3},{%4,%5,%6,%7},{%8,%9},{%0,%1,%2,%3};" \
    : "+f"((c)[0]), "+f"((c)[1]), "+f"((c)[2]), "+f"((c)[3]) \
    : "r"((a)[0]), "r"((a)[1]), "r"((a)[2]), "r"((a)[3]), \
      "r"((b)[0]), "r"((b)[1]))

#define LDS4(r, addr) asm volatile("ld.shared.v4.b32 {%0,%1,%2,%3}, [%4];" \
    : "=r"((r)[0]), "=r"((r)[1]), "=r"((r)[2]), "=r"((r)[3]) : "r"(addr))
#define LDS2(r, addr) asm volatile("ld.shared.v2.b32 {%0,%1}, [%2];" \
    : "=r"((r)[0]), "=r"((r)[1]) : "r"(addr))

// ---- fragment-layout smem indices (float index within a tile, raw fp32) ----
// A tile 128(m) x 32(k): 32 blocks of 136 floats (8-float pad, 16B-aligned).
__device__ __forceinline__ int idxA(int m, int k) {
    return (((k >> 3) * 8 + (m >> 4)) * 136)
         + (((m & 7) * 4 + (k & 3)) << 2) + ((m >> 3) & 1) + (((k >> 2) & 1) << 1);
}
// B tile 32(k) x 128(n): 64 blocks of 66 floats (2-float pad, 8B-aligned).
__device__ __forceinline__ int idxB(int k, int n) {
    return (((k >> 3) * 16 + (n >> 3)) * 66)
         + (((n & 7) * 4 + (k & 3)) << 1) + ((k >> 2) & 1);
}
#define ASZ 4352          // 32 * 136 floats
#define BSZ 4224          // 64 * 66 floats
#define BUF (ASZ + BSZ)
static constexpr size_t SMEMB = (size_t)(2 * BUF) * 4;   // 68608 B

// one 32-K chunk, 3xTF32, pass-major MMA order (16 indep accs between reuses)
__device__ __forceinline__ void chunk_mma3(uint32_t buf, int wm, int wn, int lane,
                                           float acc[4][4][4]) {
    #pragma unroll
    for (int kt = 0; kt < 4; kt++) {
        uint32_t ar[4][4], br[4][2];
        #pragma unroll
        for (int i = 0; i < 4; i++) {
            uint32_t ad = buf + (uint32_t)(((kt * 8 + wm * 4 + i) * 136 + (lane << 2)) * 4);
            LDS4(ar[i], ad);
        }
        #pragma unroll
        for (int j = 0; j < 4; j++) {
            uint32_t ad = buf + (uint32_t)((ASZ + (kt * 16 + wn * 4 + j) * 66 + (lane << 1)) * 4);
            LDS2(br[j], ad);
        }
        uint32_t ah[4][4], al[4][4], bh[4][2], bl[4][2];
        #pragma unroll
        for (int i = 0; i < 4; i++)
            #pragma unroll
            for (int r = 0; r < 4; r++) {
                float f = __uint_as_float(ar[i][r]);
                float h = to_tf32(f);
                ah[i][r] = __float_as_uint(h);
                al[i][r] = __float_as_uint(f - h);   // HW truncates to tf32
            }
        #pragma unroll
        for (int j = 0; j < 4; j++)
            #pragma unroll
            for (int r = 0; r < 2; r++) {
                float f = __uint_as_float(br[j][r]);
                float h = to_tf32(f);
                bh[j][r] = __float_as_uint(h);
                bl[j][r] = __float_as_uint(f - h);
            }
        // pass-major: consecutive MMAs touch different accumulators
        #pragma unroll
        for (int i = 0; i < 4; i++)
            #pragma unroll
            for (int j = 0; j < 4; j++)
                MMA8(acc[i][j], al[i], bh[j]);
        #pragma unroll
        for (int i = 0; i < 4; i++)
            #pragma unroll
            for (int j = 0; j < 4; j++)
                MMA8(acc[i][j], ah[i], bl[j]);
        #pragma unroll
        for (int i = 0; i < 4; i++)
            #pragma unroll
            for (int j = 0; j < 4; j++)
                MMA8(acc[i][j], ah[i], bh[j]);
    }
}

// ============================================================================
// QK: W[t,s] = ALPHA * sum_c Q[c,t] K[c,s].  M=t, N=s, K=c (4 chunks)
// ============================================================================
__global__ __launch_bounds__(256, 1)
void qk_tc(const float* __restrict__ Qm, const float* __restrict__ Km) {
    extern __shared__ float sm[];
    const int tid = threadIdx.x, w = tid >> 5, lane = tid & 31;
    const int wm = w >> 2, wn = w & 3;
    const int bh = blockIdx.z, t0 = blockIdx.y * 128, s0 = blockIdx.x * 128;
    const float* Qh = Qm + (size_t)bh * CH * LL;
    const float* Kh = Km + (size_t)bh * CH * LL;
    float* Wh = g_W + (size_t)bh * LL * LL;

    const uint32_t su = smem_u32(sm);
    float acc[4][4][4] = {};
    float rA[16], rB[16];
    const int mA = w * 16 + (lane & 15);
    const int kof = lane >> 4;

    #pragma unroll
    for (int it = 0; it < 16; it++) {
        int k = it * 2 + kof;
        rA[it] = Qh[(size_t)k * LL + t0 + mA];
        rB[it] = Kh[(size_t)k * LL + s0 + mA];
    }
    #pragma unroll
    for (int it = 0; it < 16; it++) {
        int k = it * 2 + kof;
        sm[idxA(mA, k)] = rA[it];
        sm[ASZ + idxB(k, mA)] = rB[it];
    }
    __syncthreads();

    for (int ch = 0; ch < 4; ch++) {
        if (ch + 1 < 4) {
            const int c0 = (ch + 1) * 32;
            #pragma unroll
            for (int it = 0; it < 16; it++) {
                int k = c0 + it * 2 + kof;
                rA[it] = Qh[(size_t)k * LL + t0 + mA];
                rB[it] = Kh[(size_t)k * LL + s0 + mA];
            }
        }
        chunk_mma3(su + (uint32_t)((ch & 1) * BUF * 4), wm, wn, lane, acc);
        if (ch + 1 < 4) {
            float* bb = sm + ((ch + 1) & 1) * BUF;
            #pragma unroll
            for (int it = 0; it < 16; it++) {
                int k = it * 2 + kof;
                bb[idxA(mA, k)] = rA[it];
                bb[ASZ + idxB(k, mA)] = rB[it];
            }
            __syncthreads();
        }
    }

    const int r = lane >> 2, cb = (lane & 3) * 2;
    #pragma unroll
    for (int i = 0; i < 4; i++) {
        const int row = t0 + wm * 64 + i * 16 + r;
        #pragma unroll
        for (int j = 0; j < 4; j++) {
            const int col = s0 + wn * 32 + j * 8 + cb;
            *(float2*)(Wh + (size_t)row * LL + col) =
                make_float2(acc[i][j][0] * ALPHA, acc[i][j][1] * ALPHA);
            *(float2*)(Wh + (size_t)(row + 8) * LL + col) =
                make_float2(acc[i][j][2] * ALPHA, acc[i][j][3] * ALPHA);
        }
    }
}

// ============================================================================
// AV: Out[c,t] = sum_s W[t,s] V[c,s].  M=c, N=t, K=s (32 chunks)
// ============================================================================
__global__ __launch_bounds__(256, 1)
void av_tc(const float* __restrict__ V, float* __restrict__ Out) {
    extern __shared__ float sm[];
    const int tid = threadIdx.x, w = tid >> 5, lane = tid & 31;
    const int wm = w >> 2, wn = w & 3;
    const int bh = blockIdx.z, t0 = blockIdx.x * 128;
    const float* Vh = V + (size_t)bh * CH * LL;
    const float* Wh = g_W + (size_t)bh * LL * LL;
    float* Oh = Out + (size_t)bh * CH * LL;

    const uint32_t su = smem_u32(sm);
    float acc[4][4][4] = {};
    float rA[16], rB[16];

    #pragma unroll
    for (int it = 0; it < 16; it++) {
        rA[it] = Vh[(size_t)(it * 8 + w) * LL + lane];
        rB[it] = Wh[(size_t)(t0 + it * 8 + w) * LL + lane];
    }
    #pragma unroll
    for (int it = 0; it < 16; it++) {
        sm[idxA(it * 8 + w, lane)] = rA[it];
        sm[ASZ + idxB(lane, it * 8 + w)] = rB[it];
    }
    __syncthreads();

    for (int ch = 0; ch < 32; ch++) {
        if (ch + 1 < 32) {
            const int s0 = (ch + 1) * 32;
            #pragma unroll
            for (int it = 0; it < 16; it++) {
                rA[it] = Vh[(size_t)(it * 8 + w) * LL + s0 + lane];
                rB[it] = Wh[(size_t)(t0 + it * 8 + w) * LL + s0 + lane];
            }
        }
        chunk_mma3(su + (uint32_t)((ch & 1) * BUF * 4), wm, wn, lane, acc);
        if (ch + 1 < 32) {
            float* bb = sm + ((ch + 1) & 1) * BUF;
            #pragma unroll
            for (int it = 0; it < 16; it++) {
                bb[idxA(it * 8 + w, lane)] = rA[it];
                bb[ASZ + idxB(lane, it * 8 + w)] = rB[it];
            }
            __syncthreads();
        }
    }

    const int r = lane >> 2, cb = (lane & 3) * 2;
    #pragma unroll
    for (int i = 0; i < 4; i++) {
        const int row = wm * 64 + i * 16 + r;
        #pragma unroll
        for (int j = 0; j < 4; j++) {
            const int col = t0 + wn * 32 + j * 8 + cb;
            *(float2*)(Oh + (size_t)row * LL + col) = make_float2(acc[i][j][0], acc[i][j][1]);
            *(float2*)(Oh + (size_t)(row + 8) * LL + col) = make_float2(acc[i][j][2], acc[i][j][3]);
        }
    }
}

// ============================================================================
// conv 1x1: X[o,l] = sum_c Wc[o,c] E[c,l] + bias[o].  M=o, N=l, K=c (16 chunks)
// ============================================================================
__global__ __launch_bounds__(256, 1)
void conv_tc(const float* __restrict__ Wc, const float* __restrict__ Ein,
             const float* __restrict__ bias) {
    extern __shared__ float sm[];
    const int tid = threadIdx.x, w = tid >> 5, lane = tid & 31;
    const int wm = w >> 2, wn = w & 3;
    const int b = blockIdx.z, o0 = blockIdx.y * 128, l0 = blockIdx.x * 128;
    const float* Eb = Ein + (size_t)b * Cc * LL;
    float* Xb = g_x + (size_t)b * Cc * LL;

    const uint32_t su = smem_u32(sm);
    float acc[4][4][4] = {};
    float rA[16], rB[16];
    const int nB = w * 16 + (lane & 15);
    const int kof = lane >> 4;

    #pragma unroll
    for (int it = 0; it < 16; it++) {
        rA[it] = Wc[(size_t)(o0 + it * 8 + w) * Cc + lane];
        rB[it] = Eb[(size_t)(it * 2 + kof) * LL + l0 + nB];
    }
    #pragma unroll
    for (int it = 0; it < 16; it++) {
        sm[idxA(it * 8 + w, lane)] = rA[it];
        sm[ASZ + idxB(it * 2 + kof, nB)] = rB[it];
    }
    __syncthreads();

    for (int ch = 0; ch < 16; ch++) {
        if (ch + 1 < 16) {
            const int c0 = (ch + 1) * 32;
            #pragma unroll
            for (int it = 0; it < 16; it++) {
                rA[it] = Wc[(size_t)(o0 + it * 8 + w) * Cc + c0 + lane];
                rB[it] = Eb[(size_t)(c0 + it * 2 + kof) * LL + l0 + nB];
            }
        }
        chunk_mma3(su + (uint32_t)((ch & 1) * BUF * 4), wm, wn, lane, acc);
        if (ch + 1 < 16) {
            float* bb = sm + ((ch + 1) & 1) * BUF;
            #pragma unroll
            for (int it = 0; it < 16; it++) {
                bb[idxA(it * 8 + w, lane)] = rA[it];
                bb[ASZ + idxB(it * 2 + kof, nB)] = rB[it];
            }
            __syncthreads();
        }
    }

    const int r = lane >> 2, cb = (lane & 3) * 2;
    #pragma unroll
    for (int i = 0; i < 4; i++) {
        const int o = o0 + wm * 64 + i * 16 + r;
        const float b0 = bias[o], b1 = bias[o + 8];
        #pragma unroll
        for (int j = 0; j < 4; j++) {
            const int col = l0 + wn * 32 + j * 8 + cb;
            *(float2*)(Xb + (size_t)o * LL + col) =
                make_float2(acc[i][j][0] + b0, acc[i][j][1] + b0);
            *(float2*)(Xb + (size_t)(o + 8) * LL + col) =
                make_float2(acc[i][j][2] + b1, acc[i][j][3] + b1);
        }
    }
}

// ============================================================================
// Row softmax (fp32 output; AV splits at MMA time)
// ============================================================================
__global__ __launch_bounds__(256)
void softmax_rows() {
    float* p = g_W + (size_t)blockIdx.x * LL;
    const int tid = threadIdx.x;
    float4 v = *(const float4*)(p + tid * 4);

    float m = fmaxf(fmaxf(v.x, v.y), fmaxf(v.z, v.w));
    #pragma unroll
    for (int o = 16; o; o >>= 1) m = fmaxf(m, __shfl_xor_sync(~0u, m, o));
    __shared__ float redm[8], reds[8];
    if ((tid & 31) == 0) redm[tid >> 5] = m;
    __syncthreads();
    float mx = redm[0];
    #pragma unroll
    for (int w = 1; w < 8; w++) mx = fmaxf(mx, redm[w]);

    v.x = expf(v.x - mx); v.y = expf(v.y - mx);
    v.z = expf(v.z - mx); v.w = expf(v.w - mx);
    float s = v.x + v.y + v.z + v.w;
    #pragma unroll
    for (int o = 16; o; o >>= 1) s += __shfl_xor_sync(~0u, s, o);
    if ((tid & 31) == 0) reds[tid >> 5] = s;
    __syncthreads();
    float st = 0.f;
    #pragma unroll
    for (int w = 0; w < 8; w++) st += reds[w];

    float inv = 1.0f / st;
    v.x *= inv; v.y *= inv; v.z *= inv; v.w *= inv;
    *(float4*)(p + tid * 4) = v;
}

// ============================================================================
// BN stats + normalize + swish
// ============================================================================
__global__ __launch_bounds__(256)
void bn_stats() {
    const int o = blockIdx.x;
    float s = 0.f, sq = 0.f;
    for (int idx = threadIdx.x; idx < Bb * LL; idx += 256) {
        const int b = idx >> 10, l = idx & (LL - 1);
        float x = g_x[((size_t)b * Cc + o) * LL + l];
        s += x; sq += x * x;
    }
    __shared__ float rs[256], rq[256];
    rs[threadIdx.x] = s; rq[threadIdx.x] = sq;
    __syncthreads();
    for (int st = 128; st; st >>= 1) {
        if (threadIdx.x < st) {
            rs[threadIdx.x] += rs[threadIdx.x + st];
            rq[threadIdx.x] += rq[threadIdx.x + st];
        }
        __syncthreads();
    }
    if (threadIdx.x == 0) {
        const float n = (float)(Bb * LL);
        float mean = rs[0] / n;
        float var  = rq[0] / n - mean * mean;
        g_stats[o] = mean;
        g_stats[Cc + o] = rsqrtf(var + 1e-5f);
    }
}

__global__ __launch_bounds__(256)
void bn_swish(const float* __restrict__ gamma, const float* __restrict__ beta,
              float* __restrict__ out) {
    const size_t i = ((size_t)blockIdx.x * blockDim.x + threadIdx.x) * 4;
    const int o = (int)((i >> 10) & (Cc - 1));
    const float m = g_stats[o], is = g_stats[Cc + o];
    const float ga = gamma[o], be = beta[o];
    float4 x = *(const float4*)(g_x + i);
    float4 y;
    { float xn = (x.x - m) * is * ga + be; y.x = xn / (1.f + expf(-xn)); }
    { float xn = (x.y - m) * is * ga + be; y.y = xn / (1.f + expf(-xn)); }
    { float xn = (x.z - m) * is * ga + be; y.z = xn / (1.f + expf(-xn)); }
    { float xn = (x.w - m) * is * ga + be; y.w = xn / (1.f + expf(-xn)); }
    *(float4*)(out + i) = y;
}

// ============================================================================
// launch
// ============================================================================
extern "C" void kernel_launch(void* const* d_in, const int* in_sizes, int n_in,
                              void* d_out, int out_size) {
    const float* c_in   = (const float*)d_in[0];
    const float* e_in   = (const float*)d_in[1];
    const float* conv_w = (const float*)d_in[2];
    const float* conv_b = (const float*)d_in[3];
    const float* gamma  = (const float*)d_in[4];
    const float* beta   = (const float*)d_in[5];
    float* out = (float*)d_out;

    float *t1 = nullptr, *t2 = nullptr;
    cudaGetSymbolAddress((void**)&t1, g_t1);
    cudaGetSymbolAddress((void**)&t2, g_t2);

    cudaFuncSetAttribute(qk_tc,   cudaFuncAttributeMaxDynamicSharedMemorySize, (int)SMEMB);
    cudaFuncSetAttribute(av_tc,   cudaFuncAttributeMaxDynamicSharedMemorySize, (int)SMEMB);
    cudaFuncSetAttribute(conv_tc, cudaFuncAttributeMaxDynamicSharedMemorySize, (int)SMEMB);

    // attn1: _c = attn(q=e, k=c, v=c)
    qk_tc<<<dim3(8, 8, BH), 256, SMEMB>>>(e_in, c_in);
    softmax_rows<<<BH * LL, 256>>>();
    av_tc<<<dim3(8, 1, BH), 256, SMEMB>>>(c_in, t1);

    // attn2: _e = attn(q=_c, k=e, v=e)
    qk_tc<<<dim3(8, 8, BH), 256, SMEMB>>>(t1, e_in);
    softmax_rows<<<BH * LL, 256>>>();
    av_tc<<<dim3(8, 1, BH), 256, SMEMB>>>(e_in, t2);

    // proj: 1x1 conv + bias, then BN + swish
    conv_tc<<<dim3(8, 4, 8), 256, SMEMB>>>(conv_w, t2, conv_b);
    bn_stats<<<Cc, 256>>>();
    bn_swish<<<(Bb * Cc * LL) / (256 * 4), 256>>>(gamma, beta, out);
}

// round 7
// speedup vs baseline: 1.2629x; 1.0021x over previous
#include <cuda_runtime.h>
#include <cstdint>
#include <math.h>

#define Bb 8
#define Cc 512
#define CH 128
#define LL 1024
#define BH 32
#define ALPHA 0.088388347648318447f   // 1/sqrt(128)

// ---------------- device scratch ----------------
__device__ float g_W[(size_t)BH * LL * LL];
__device__ float g_t1[(size_t)Bb * Cc * LL];
__device__ float g_t2[(size_t)Bb * Cc * LL];
__device__ float g_x [(size_t)Bb * Cc * LL];
__device__ float g_stats[2 * Cc];

// ==================== helpers ====================
__device__ __forceinline__ uint32_t smem_u32(const void* p) {
    uint32_t a;
    asm("{ .reg .u64 t; cvta.to.shared.u64 t, %1; cvt.u32.u64 %0, t; }" : "=r"(a) : "l"(p));
    return a;
}
__device__ __forceinline__ float to_tf32(float x) {
    uint32_t o;
    asm("cvt.rna.tf32.f32 %0, %1;" : "=r"(o) : "f"(x));
    return __uint_as_float(o);
}

#define MMA8(c, a, b) asm volatile( \
    "mma.sync.aligned.m16n8k8.row.col.f32.tf32.tf32.f32 " \
    "{%0,%1,%2,%3},{%4,%5,%6,%7},{%8,%9},{%0,%1,%2,%3};" \
    : "+f"((c)[0]), "+f"((c)[1]), "+f"((c)[2]), "+f"((c)[3]) \
    : "r"((a)[0]), "r"((a)[1]), "r"((a)[2]), "r"((a)[3]), \
      "r"((b)[0]), "r"((b)[1]))

#define LDS4(r, addr) asm volatile("ld.shared.v4.b32 {%0,%1,%2,%3}, [%4];" \
    : "=r"((r)[0]), "=r"((r)[1]), "=r"((r)[2]), "=r"((r)[3]) : "r"(addr))
#define LDS2(r, addr) asm volatile("ld.shared.v2.b32 {%0,%1}, [%2];" \
    : "=r"((r)[0]), "=r"((r)[1]) : "r"(addr))

// ---- fragment-layout smem indices (float index within a tile, raw fp32) ----
// A tile 128(m) x 32(k): 32 blocks of 136 floats (8-float pad, 16B-aligned).
__device__ __forceinline__ int idxA(int m, int k) {
    return (((k >> 3) * 8 + (m >> 4)) * 136)
         + (((m & 7) * 4 + (k & 3)) << 2) + ((m >> 3) & 1) + (((k >> 2) & 1) << 1);
}
// B tile 32(k) x 128(n): 64 blocks of 66 floats (2-float pad, 8B-aligned).
__device__ __forceinline__ int idxB(int k, int n) {
    return (((k >> 3) * 16 + (n >> 3)) * 66)
         + (((n & 7) * 4 + (k & 3)) << 1) + ((k >> 2) & 1);
}
#define ASZ 4352          // 32 * 136 floats
#define BSZ 4224          // 64 * 66 floats
#define BUF (ASZ + BSZ)
static constexpr size_t SMEMB = (size_t)BUF * 4;   // 34304 B single buffer

// one 32-K chunk, 3xTF32, in-register hi/lo split
__device__ __forceinline__ void chunk_mma3(uint32_t buf, int wm, int wn, int lane,
                                           float acc[4][4][4]) {
    #pragma unroll
    for (int kt = 0; kt < 4; kt++) {
        uint32_t ar[4][4], br[4][2];
        #pragma unroll
        for (int i = 0; i < 4; i++) {
            uint32_t ad = buf + (uint32_t)(((kt * 8 + wm * 4 + i) * 136 + (lane << 2)) * 4);
            LDS4(ar[i], ad);
        }
        #pragma unroll
        for (int j = 0; j < 4; j++) {
            uint32_t ad = buf + (uint32_t)((ASZ + (kt * 16 + wn * 4 + j) * 66 + (lane << 1)) * 4);
            LDS2(br[j], ad);
        }
        uint32_t ah[4][4], al[4][4], bh[4][2], bl[4][2];
        #pragma unroll
        for (int i = 0; i < 4; i++)
            #pragma unroll
            for (int r = 0; r < 4; r++) {
                float f = __uint_as_float(ar[i][r]);
                float h = to_tf32(f);
                ah[i][r] = __float_as_uint(h);
                al[i][r] = __float_as_uint(f - h);   // HW truncates to tf32
            }
        #pragma unroll
        for (int j = 0; j < 4; j++)
            #pragma unroll
            for (int r = 0; r < 2; r++) {
                float f = __uint_as_float(br[j][r]);
                float h = to_tf32(f);
                bh[j][r] = __float_as_uint(h);
                bl[j][r] = __float_as_uint(f - h);
            }
        #pragma unroll
        for (int i = 0; i < 4; i++)
            #pragma unroll
            for (int j = 0; j < 4; j++) {
                MMA8(acc[i][j], al[i], bh[j]);
                MMA8(acc[i][j], ah[i], bl[j]);
                MMA8(acc[i][j], ah[i], bh[j]);
            }
    }
}

// ============================================================================
// QK: W[t,s] = ALPHA * sum_c Q[c,t] K[c,s].  M=t, N=s, K=c (4 chunks)
// ============================================================================
__global__ __launch_bounds__(256, 2)
void qk_tc(const float* __restrict__ Qm, const float* __restrict__ Km) {
    extern __shared__ float sm[];
    const int tid = threadIdx.x, w = tid >> 5, lane = tid & 31;
    const int wm = w >> 2, wn = w & 3;
    const int bh = blockIdx.z, t0 = blockIdx.y * 128, s0 = blockIdx.x * 128;
    const float* Qh = Qm + (size_t)bh * CH * LL;
    const float* Kh = Km + (size_t)bh * CH * LL;
    float* Wh = g_W + (size_t)bh * LL * LL;

    const uint32_t su = smem_u32(sm);
    float acc[4][4][4] = {};
    const int mA = w * 16 + (lane & 15);
    const int kof = lane >> 4;

    for (int ch = 0; ch < 4; ch++) {
        const int c0 = ch * 32;
        if (ch > 0) __syncthreads();           // previous compute done
        #pragma unroll
        for (int it = 0; it < 16; it++) {
            int k = it * 2 + kof;
            sm[idxA(mA, k)]       = Qh[(size_t)(c0 + k) * LL + t0 + mA];
            sm[ASZ + idxB(k, mA)] = Kh[(size_t)(c0 + k) * LL + s0 + mA];
        }
        __syncthreads();
        chunk_mma3(su, wm, wn, lane, acc);
    }

    const int r = lane >> 2, cb = (lane & 3) * 2;
    #pragma unroll
    for (int i = 0; i < 4; i++) {
        const int row = t0 + wm * 64 + i * 16 + r;
        #pragma unroll
        for (int j = 0; j < 4; j++) {
            const int col = s0 + wn * 32 + j * 8 + cb;
            *(float2*)(Wh + (size_t)row * LL + col) =
                make_float2(acc[i][j][0] * ALPHA, acc[i][j][1] * ALPHA);
            *(float2*)(Wh + (size_t)(row + 8) * LL + col) =
                make_float2(acc[i][j][2] * ALPHA, acc[i][j][3] * ALPHA);
        }
    }
}

// ============================================================================
// AV: Out[c,t] = sum_s W[t,s] V[c,s].  M=c, N=t, K=s (32 chunks)
// ============================================================================
__global__ __launch_bounds__(256, 2)
void av_tc(const float* __restrict__ V, float* __restrict__ Out) {
    extern __shared__ float sm[];
    const int tid = threadIdx.x, w = tid >> 5, lane = tid & 31;
    const int wm = w >> 2, wn = w & 3;
    const int bh = blockIdx.z, t0 = blockIdx.x * 128;
    const float* Vh = V + (size_t)bh * CH * LL;
    const float* Wh = g_W + (size_t)bh * LL * LL;
    float* Oh = Out + (size_t)bh * CH * LL;

    const uint32_t su = smem_u32(sm);
    float acc[4][4][4] = {};

    for (int ch = 0; ch < 32; ch++) {
        const int s0 = ch * 32;
        if (ch > 0) __syncthreads();
        #pragma unroll
        for (int it = 0; it < 16; it++) {
            int m = it * 8 + w;
            sm[idxA(m, lane)]       = Vh[(size_t)m * LL + s0 + lane];
            sm[ASZ + idxB(lane, m)] = Wh[(size_t)(t0 + m) * LL + s0 + lane];
        }
        __syncthreads();
        chunk_mma3(su, wm, wn, lane, acc);
    }

    const int r = lane >> 2, cb = (lane & 3) * 2;
    #pragma unroll
    for (int i = 0; i < 4; i++) {
        const int row = wm * 64 + i * 16 + r;
        #pragma unroll
        for (int j = 0; j < 4; j++) {
            const int col = t0 + wn * 32 + j * 8 + cb;
            *(float2*)(Oh + (size_t)row * LL + col) = make_float2(acc[i][j][0], acc[i][j][1]);
            *(float2*)(Oh + (size_t)(row + 8) * LL + col) = make_float2(acc[i][j][2], acc[i][j][3]);
        }
    }
}

// ============================================================================
// conv 1x1: X[o,l] = sum_c Wc[o,c] E[c,l] + bias[o].  M=o, N=l, K=c (16 chunks)
// ============================================================================
__global__ __launch_bounds__(256, 2)
void conv_tc(const float* __restrict__ Wc, const float* __restrict__ Ein,
             const float* __restrict__ bias) {
    extern __shared__ float sm[];
    const int tid = threadIdx.x, w = tid >> 5, lane = tid & 31;
    const int wm = w >> 2, wn = w & 3;
    const int b = blockIdx.z, o0 = blockIdx.y * 128, l0 = blockIdx.x * 128;
    const float* Eb = Ein + (size_t)b * Cc * LL;
    float* Xb = g_x + (size_t)b * Cc * LL;

    const uint32_t su = smem_u32(sm);
    float acc[4][4][4] = {};
    const int nB = w * 16 + (lane & 15);
    const int kof = lane >> 4;

    for (int ch = 0; ch < 16; ch++) {
        const int c0 = ch * 32;
        if (ch > 0) __syncthreads();
        #pragma unroll
        for (int it = 0; it < 16; it++) {
            int m = it * 8 + w;
            int k = it * 2 + kof;
            sm[idxA(m, lane)]      = Wc[(size_t)(o0 + m) * Cc + c0 + lane];
            sm[ASZ + idxB(k, nB)]  = Eb[(size_t)(c0 + k) * LL + l0 + nB];
        }
        __syncthreads();
        chunk_mma3(su, wm, wn, lane, acc);
    }

    const int r = lane >> 2, cb = (lane & 3) * 2;
    #pragma unroll
    for (int i = 0; i < 4; i++) {
        const int o = o0 + wm * 64 + i * 16 + r;
        const float b0 = bias[o], b1 = bias[o + 8];
        #pragma unroll
        for (int j = 0; j < 4; j++) {
            const int col = l0 + wn * 32 + j * 8 + cb;
            *(float2*)(Xb + (size_t)o * LL + col) =
                make_float2(acc[i][j][0] + b0, acc[i][j][1] + b0);
            *(float2*)(Xb + (size_t)(o + 8) * LL + col) =
                make_float2(acc[i][j][2] + b1, acc[i][j][3] + b1);
        }
    }
}

// ============================================================================
// Row softmax (fp32 output; AV splits at MMA time)
// ============================================================================
__global__ __launch_bounds__(256)
void softmax_rows() {
    float* p = g_W + (size_t)blockIdx.x * LL;
    const int tid = threadIdx.x;
    float4 v = *(const float4*)(p + tid * 4);

    float m = fmaxf(fmaxf(v.x, v.y), fmaxf(v.z, v.w));
    #pragma unroll
    for (int o = 16; o; o >>= 1) m = fmaxf(m, __shfl_xor_sync(~0u, m, o));
    __shared__ float redm[8], reds[8];
    if ((tid & 31) == 0) redm[tid >> 5] = m;
    __syncthreads();
    float mx = redm[0];
    #pragma unroll
    for (int w = 1; w < 8; w++) mx = fmaxf(mx, redm[w]);

    v.x = expf(v.x - mx); v.y = expf(v.y - mx);
    v.z = expf(v.z - mx); v.w = expf(v.w - mx);
    float s = v.x + v.y + v.z + v.w;
    #pragma unroll
    for (int o = 16; o; o >>= 1) s += __shfl_xor_sync(~0u, s, o);
    if ((tid & 31) == 0) reds[tid >> 5] = s;
    __syncthreads();
    float st = 0.f;
    #pragma unroll
    for (int w = 0; w < 8; w++) st += reds[w];

    float inv = 1.0f / st;
    v.x *= inv; v.y *= inv; v.z *= inv; v.w *= inv;
    *(float4*)(p + tid * 4) = v;
}

// ============================================================================
// BN stats + normalize + swish
// ============================================================================
__global__ __launch_bounds__(256)
void bn_stats() {
    const int o = blockIdx.x;
    float s = 0.f, sq = 0.f;
    for (int idx = threadIdx.x; idx < Bb * LL; idx += 256) {
        const int b = idx >> 10, l = idx & (LL - 1);
        float x = g_x[((size_t)b * Cc + o) * LL + l];
        s += x; sq += x * x;
    }
    __shared__ float rs[256], rq[256];
    rs[threadIdx.x] = s; rq[threadIdx.x] = sq;
    __syncthreads();
    for (int st = 128; st; st >>= 1) {
        if (threadIdx.x < st) {
            rs[threadIdx.x] += rs[threadIdx.x + st];
            rq[threadIdx.x] += rq[threadIdx.x + st];
        }
        __syncthreads();
    }
    if (threadIdx.x == 0) {
        const float n = (float)(Bb * LL);
        float mean = rs[0] / n;
        float var  = rq[0] / n - mean * mean;
        g_stats[o] = mean;
        g_stats[Cc + o] = rsqrtf(var + 1e-5f);
    }
}

__global__ __launch_bounds__(256)
void bn_swish(const float* __restrict__ gamma, const float* __restrict__ beta,
              float* __restrict__ out) {
    const size_t i = ((size_t)blockIdx.x * blockDim.x + threadIdx.x) * 4;
    const int o = (int)((i >> 10) & (Cc - 1));
    const float m = g_stats[o], is = g_stats[Cc + o];
    const float ga = gamma[o], be = beta[o];
    float4 x = *(const float4*)(g_x + i);
    float4 y;
    { float xn = (x.x - m) * is * ga + be; y.x = xn / (1.f + expf(-xn)); }
    { float xn = (x.y - m) * is * ga + be; y.y = xn / (1.f + expf(-xn)); }
    { float xn = (x.z - m) * is * ga + be; y.z = xn / (1.f + expf(-xn)); }
    { float xn = (x.w - m) * is * ga + be; y.w = xn / (1.f + expf(-xn)); }
    *(float4*)(out + i) = y;
}

// ============================================================================
// launch
// ============================================================================
extern "C" void kernel_launch(void* const* d_in, const int* in_sizes, int n_in,
                              void* d_out, int out_size) {
    const float* c_in   = (const float*)d_in[0];
    const float* e_in   = (const float*)d_in[1];
    const float* conv_w = (const float*)d_in[2];
    const float* conv_b = (const float*)d_in[3];
    const float* gamma  = (const float*)d_in[4];
    const float* beta   = (const float*)d_in[5];
    float* out = (float*)d_out;

    float *t1 = nullptr, *t2 = nullptr;
    cudaGetSymbolAddress((void**)&t1, g_t1);
    cudaGetSymbolAddress((void**)&t2, g_t2);

    cudaFuncSetAttribute(qk_tc,   cudaFuncAttributeMaxDynamicSharedMemorySize, (int)SMEMB);
    cudaFuncSetAttribute(av_tc,   cudaFuncAttributeMaxDynamicSharedMemorySize, (int)SMEMB);
    cudaFuncSetAttribute(conv_tc, cudaFuncAttributeMaxDynamicSharedMemorySize, (int)SMEMB);

    // attn1: _c = attn(q=e, k=c, v=c)
    qk_tc<<<dim3(8, 8, BH), 256, SMEMB>>>(e_in, c_in);
    softmax_rows<<<BH * LL, 256>>>();
    av_tc<<<dim3(8, 1, BH), 256, SMEMB>>>(c_in, t1);

    // attn2: _e = attn(q=_c, k=e, v=e)
    qk_tc<<<dim3(8, 8, BH), 256, SMEMB>>>(t1, e_in);
    softmax_rows<<<BH * LL, 256>>>();
    av_tc<<<dim3(8, 1, BH), 256, SMEMB>>>(e_in, t2);

    // proj: 1x1 conv + bias, then BN + swish
    conv_tc<<<dim3(8, 4, 8), 256, SMEMB>>>(conv_w, t2, conv_b);
    bn_stats<<<Cc, 256>>>();
    bn_swish<<<(Bb * Cc * LL) / (256 * 4), 256>>>(gamma, beta, out);
}

// round 8
// speedup vs baseline: 1.9695x; 1.5595x over previous
#include <cuda_runtime.h>
#include <cuda_bf16.h>
#include <cstdint>
#include <math.h>

#define Bb 8
#define Cc 512
#define CH 128
#define LL 1024
#define BH 32
#define ALPHA 0.088388347648318447f   // 1/sqrt(128)

// ---------------- device scratch ----------------
__device__ float    g_W [(size_t)BH * LL * LL];   // fp32 scores
__device__ uint32_t g_W2[(size_t)BH * LL * LL];   // packed (hi,lo) bf16 softmax(W)
__device__ uint32_t g_c2 [(size_t)Bb * Cc * LL];
__device__ uint32_t g_e2 [(size_t)Bb * Cc * LL];
__device__ uint32_t g_t12[(size_t)Bb * Cc * LL];
__device__ uint32_t g_t22[(size_t)Bb * Cc * LL];
__device__ uint32_t g_cw2[Cc * Cc];
__device__ float    g_x [(size_t)Bb * Cc * LL];
__device__ float    g_stats[2 * Cc];

// ==================== helpers ====================
__device__ __forceinline__ uint32_t smem_u32(const void* p) {
    uint32_t a;
    asm("{ .reg .u64 t; cvta.to.shared.u64 t, %1; cvt.u32.u64 %0, t; }" : "=r"(a) : "l"(p));
    return a;
}
// fp32 -> packed (hi bf16 @[15:0], lo bf16 @[31:16])
__device__ __forceinline__ uint32_t splt(float x) {
    __nv_bfloat16 h = __float2bfloat16_rn(x);
    float hf = __bfloat162float(h);
    __nv_bfloat16 l = __float2bfloat16_rn(x - hf);
    return (uint32_t)__bfloat16_as_ushort(h) | ((uint32_t)__bfloat16_as_ushort(l) << 16);
}
// two packed elems (k, k+1) -> bf16x2 hi-pair and lo-pair
__device__ __forceinline__ void pack2(uint32_t e0, uint32_t e1, uint32_t& h, uint32_t& l) {
    h = __byte_perm(e0, e1, 0x5410);
    l = __byte_perm(e0, e1, 0x7632);
}

#define MMA16(c, a, b) asm volatile( \
    "mma.sync.aligned.m16n8k16.row.col.f32.bf16.bf16.f32 " \
    "{%0,%1,%2,%3},{%4,%5,%6,%7},{%8,%9},{%0,%1,%2,%3};" \
    : "+f"((c)[0]), "+f"((c)[1]), "+f"((c)[2]), "+f"((c)[3]) \
    : "r"((a)[0]), "r"((a)[1]), "r"((a)[2]), "r"((a)[3]), \
      "r"((b)[0]), "r"((b)[1]))

#define LDS4(r, addr) asm volatile("ld.shared.v4.b32 {%0,%1,%2,%3}, [%4];" \
    : "=r"((r)[0]), "=r"((r)[1]), "=r"((r)[2]), "=r"((r)[3]) : "r"(addr))
#define LDS2(r, addr) asm volatile("ld.shared.v2.b32 {%0,%1}, [%2];" \
    : "=r"((r)[0]), "=r"((r)[1]) : "r"(addr))
#define STS128(addr, a, b, c, d) asm volatile("st.shared.v4.b32 [%0], {%1,%2,%3,%4};" \
    :: "r"(addr), "r"(a), "r"(b), "r"(c), "r"(d))
#define STS64(addr, a, b) asm volatile("st.shared.v2.b32 [%0], {%1,%2};" \
    :: "r"(addr), "r"(a), "r"(b))

// ---- smem tile geometry (bytes) ----
// A tile 128m x 32k bf16: 16 blocks (mt*2+kt) of 512B granules + 16B pad
// B tile 32k x 128n bf16: 32 blocks (kt*16+nt) of 256B + 8B pad
#define ABLK 528
#define ATILE 8448
#define BBLK 264
#define BTILE 8448
#define SM_BHI (2 * ATILE)
#define SMEMB (2 * ATILE + 2 * BTILE)   // 33792 B

// one 32-K chunk: 2 ksteps x (12 LDS + 48 bf16 MMAs)
__device__ __forceinline__ void chunk_bf(uint32_t su, int wm, int wn, int lane,
                                         float acc[4][4][4]) {
    #pragma unroll
    for (int kt = 0; kt < 2; kt++) {
        uint32_t ah[4][4], al[4][4], bh[4][2], bl[4][2];
        #pragma unroll
        for (int i = 0; i < 4; i++) {
            uint32_t ad = su + (uint32_t)((((wm * 4 + i) << 1) + kt) * ABLK + lane * 16);
            LDS4(ah[i], ad);
            LDS4(al[i], ad + ATILE);
        }
        #pragma unroll
        for (int j = 0; j < 4; j++) {
            uint32_t bd = su + (uint32_t)(SM_BHI + (kt * 16 + wn * 4 + j) * BBLK + lane * 8);
            LDS2(bh[j], bd);
            LDS2(bl[j], bd + BTILE);
        }
        #pragma unroll
        for (int i = 0; i < 4; i++)
            #pragma unroll
            for (int j = 0; j < 4; j++) {
                MMA16(acc[i][j], al[i], bh[j]);
                MMA16(acc[i][j], ah[i], bl[j]);
                MMA16(acc[i][j], ah[i], bh[j]);
            }
    }
}

// ---- granule fill helpers: thread writes one lane-granule of a block ----
// A granule task tau in [0,512): T=tau&31, blk=tau>>5; rows r0,r0+8; cols kb..kb+1, kb+8..kb+9
// B granule task tau in [0,1024): T=tau&31, blk=tau>>5; n; k0..k0+1, k0+8..k0+9

// ============================================================================
// QK: W[t,s] = ALPHA * sum_c Q[c,t] K[c,s].  A,B element pairs stride-LL.
// ============================================================================
__global__ __launch_bounds__(256, 2)
void qk_bf(const uint32_t* __restrict__ Q2, const uint32_t* __restrict__ K2) {
    __shared__ __align__(16) char smb[SMEMB];
    const int tid = threadIdx.x, w = tid >> 5, lane = tid & 31;
    const int wm = w >> 2, wn = w & 3;
    const int bh = blockIdx.z, t0 = blockIdx.y * 128, s0 = blockIdx.x * 128;
    const uint32_t* Qh = Q2 + (size_t)bh * CH * LL;
    const uint32_t* Kh = K2 + (size_t)bh * CH * LL;
    float* Wh = g_W + (size_t)bh * LL * LL;

    const uint32_t su = smem_u32(smb);
    float acc[4][4][4] = {};

    for (int ch = 0; ch < 4; ch++) {
        const int c0 = ch * 32;
        if (ch > 0) __syncthreads();
        #pragma unroll
        for (int t = 0; t < 2; t++) {        // A tile
            int tau = tid + t * 256;
            int T = tau & 31, blk = tau >> 5;
            int r0 = ((blk >> 1) << 4) + (T >> 2);
            int kb = ((blk & 1) << 4) + ((T & 3) << 1);
            const uint32_t* Qc = Qh + (size_t)(c0 + kb) * LL + t0 + r0;
            uint32_t h0, l0, h1, l1, h2, l2, h3, l3;
            pack2(Qc[0],          Qc[LL],          h0, l0);
            pack2(Qc[8],          Qc[LL + 8],      h1, l1);
            pack2(Qc[8 * LL],     Qc[9 * LL],      h2, l2);
            pack2(Qc[8 * LL + 8], Qc[9 * LL + 8],  h3, l3);
            uint32_t ad = su + (uint32_t)(blk * ABLK + T * 16);
            STS128(ad, h0, h1, h2, h3);
            STS128(ad + ATILE, l0, l1, l2, l3);
        }
        #pragma unroll
        for (int t = 0; t < 4; t++) {        // B tile
            int tau = tid + t * 256;
            int T = tau & 31, blk = tau >> 5;
            int n  = ((blk & 15) << 3) + (T >> 2);
            int k0 = ((blk >> 4) << 4) + ((T & 3) << 1);
            const uint32_t* Kc = Kh + (size_t)(c0 + k0) * LL + s0 + n;
            uint32_t h0, l0, h1, l1;
            pack2(Kc[0],      Kc[LL],     h0, l0);
            pack2(Kc[8 * LL], Kc[9 * LL], h1, l1);
            uint32_t ad = su + (uint32_t)(SM_BHI + blk * BBLK + T * 8);
            STS64(ad, h0, h1);
            STS64(ad + BTILE, l0, l1);
        }
        __syncthreads();
        chunk_bf(su, wm, wn, lane, acc);
    }

    const int r = lane >> 2, cb = (lane & 3) * 2;
    #pragma unroll
    for (int i = 0; i < 4; i++) {
        const int row = t0 + wm * 64 + i * 16 + r;
        #pragma unroll
        for (int j = 0; j < 4; j++) {
            const int col = s0 + wn * 32 + j * 8 + cb;
            *(float2*)(Wh + (size_t)row * LL + col) =
                make_float2(acc[i][j][0] * ALPHA, acc[i][j][1] * ALPHA);
            *(float2*)(Wh + (size_t)(row + 8) * LL + col) =
                make_float2(acc[i][j][2] * ALPHA, acc[i][j][3] * ALPHA);
        }
    }
}

// ============================================================================
// AV: Out[c,t] = sum_s W[t,s] V[c,s].  All element pairs contiguous (LDG.64).
// Writes packed split output (consumed by next QK / conv).
// ============================================================================
__global__ __launch_bounds__(256, 2)
void av_bf(const uint32_t* __restrict__ V2, uint32_t* __restrict__ Out2) {
    __shared__ __align__(16) char smb[SMEMB];
    const int tid = threadIdx.x, w = tid >> 5, lane = tid & 31;
    const int wm = w >> 2, wn = w & 3;
    const int bh = blockIdx.z, t0 = blockIdx.x * 128;
    const uint32_t* Vh = V2 + (size_t)bh * CH * LL;
    const uint32_t* Wh = g_W2 + (size_t)bh * LL * LL;
    uint32_t* Oh = Out2 + (size_t)bh * CH * LL;

    const uint32_t su = smem_u32(smb);
    float acc[4][4][4] = {};

    for (int ch = 0; ch < 32; ch++) {
        const int s0 = ch * 32;
        if (ch > 0) __syncthreads();
        #pragma unroll
        for (int t = 0; t < 2; t++) {        // A = V tile
            int tau = tid + t * 256;
            int T = tau & 31, blk = tau >> 5;
            int r0 = ((blk >> 1) << 4) + (T >> 2);
            int kb = ((blk & 1) << 4) + ((T & 3) << 1);
            const uint32_t* Vc = Vh + (size_t)r0 * LL + s0 + kb;
            uint2 p0 = *(const uint2*)(Vc);
            uint2 p1 = *(const uint2*)(Vc + 8 * LL);
            uint2 p2 = *(const uint2*)(Vc + 8);
            uint2 p3 = *(const uint2*)(Vc + 8 * LL + 8);
            uint32_t h0, l0, h1, l1, h2, l2, h3, l3;
            pack2(p0.x, p0.y, h0, l0);
            pack2(p1.x, p1.y, h1, l1);
            pack2(p2.x, p2.y, h2, l2);
            pack2(p3.x, p3.y, h3, l3);
            uint32_t ad = su + (uint32_t)(blk * ABLK + T * 16);
            STS128(ad, h0, h1, h2, h3);
            STS128(ad + ATILE, l0, l1, l2, l3);
        }
        #pragma unroll
        for (int t = 0; t < 4; t++) {        // B = W^T tile
            int tau = tid + t * 256;
            int T = tau & 31, blk = tau >> 5;
            int n  = ((blk & 15) << 3) + (T >> 2);
            int k0 = ((blk >> 4) << 4) + ((T & 3) << 1);
            const uint32_t* Wc = Wh + (size_t)(t0 + n) * LL + s0 + k0;
            uint2 p0 = *(const uint2*)(Wc);
            uint2 p1 = *(const uint2*)(Wc + 8);
            uint32_t h0, l0, h1, l1;
            pack2(p0.x, p0.y, h0, l0);
            pack2(p1.x, p1.y, h1, l1);
            uint32_t ad = su + (uint32_t)(SM_BHI + blk * BBLK + T * 8);
            STS64(ad, h0, h1);
            STS64(ad + BTILE, l0, l1);
        }
        __syncthreads();
        chunk_bf(su, wm, wn, lane, acc);
    }

    const int r = lane >> 2, cb = (lane & 3) * 2;
    #pragma unroll
    for (int i = 0; i < 4; i++) {
        const int row = wm * 64 + i * 16 + r;
        #pragma unroll
        for (int j = 0; j < 4; j++) {
            const int col = t0 + wn * 32 + j * 8 + cb;
            uint2 v0 = make_uint2(splt(acc[i][j][0]), splt(acc[i][j][1]));
            uint2 v1 = make_uint2(splt(acc[i][j][2]), splt(acc[i][j][3]));
            *(uint2*)(Oh + (size_t)row * LL + col) = v0;
            *(uint2*)(Oh + (size_t)(row + 8) * LL + col) = v1;
        }
    }
}

// ============================================================================
// conv 1x1: X[o,l] = sum_c Wc[o,c] E[c,l] + bias.  A contiguous, B strided.
// ============================================================================
__global__ __launch_bounds__(256, 2)
void conv_bf(const uint32_t* __restrict__ Wc2, const uint32_t* __restrict__ E2,
             const float* __restrict__ bias) {
    __shared__ __align__(16) char smb[SMEMB];
    const int tid = threadIdx.x, w = tid >> 5, lane = tid & 31;
    const int wm = w >> 2, wn = w & 3;
    const int b = blockIdx.z, o0 = blockIdx.y * 128, l0 = blockIdx.x * 128;
    const uint32_t* Eb = E2 + (size_t)b * Cc * LL;
    float* Xb = g_x + (size_t)b * Cc * LL;

    const uint32_t su = smem_u32(smb);
    float acc[4][4][4] = {};

    for (int ch = 0; ch < 16; ch++) {
        const int c0 = ch * 32;
        if (ch > 0) __syncthreads();
        #pragma unroll
        for (int t = 0; t < 2; t++) {        // A = conv weight tile
            int tau = tid + t * 256;
            int T = tau & 31, blk = tau >> 5;
            int r0 = ((blk >> 1) << 4) + (T >> 2);
            int kb = ((blk & 1) << 4) + ((T & 3) << 1);
            const uint32_t* Ac = Wc2 + (size_t)(o0 + r0) * Cc + c0 + kb;
            uint2 p0 = *(const uint2*)(Ac);
            uint2 p1 = *(const uint2*)(Ac + 8 * Cc);
            uint2 p2 = *(const uint2*)(Ac + 8);
            uint2 p3 = *(const uint2*)(Ac + 8 * Cc + 8);
            uint32_t h0, l0, h1, l1, h2, l2, h3, l3;
            pack2(p0.x, p0.y, h0, l0);
            pack2(p1.x, p1.y, h1, l1);
            pack2(p2.x, p2.y, h2, l2);
            pack2(p3.x, p3.y, h3, l3);
            uint32_t ad = su + (uint32_t)(blk * ABLK + T * 16);
            STS128(ad, h0, h1, h2, h3);
            STS128(ad + ATILE, l0, l1, l2, l3);
        }
        #pragma unroll
        for (int t = 0; t < 4; t++) {        // B = E^T tile (pairs stride-LL)
            int tau = tid + t * 256;
            int T = tau & 31, blk = tau >> 5;
            int n  = ((blk & 15) << 3) + (T >> 2);
            int k0 = ((blk >> 4) << 4) + ((T & 3) << 1);
            const uint32_t* Ec = Eb + (size_t)(c0 + k0) * LL + l0 + n;
            uint32_t h0, l0v, h1, l1v;
            pack2(Ec[0],      Ec[LL],     h0, l0v);
            pack2(Ec[8 * LL], Ec[9 * LL], h1, l1v);
            uint32_t ad = su + (uint32_t)(SM_BHI + blk * BBLK + T * 8);
            STS64(ad, h0, h1);
            STS64(ad + BTILE, l0v, l1v);
        }
        __syncthreads();
        chunk_bf(su, wm, wn, lane, acc);
    }

    const int r = lane >> 2, cb = (lane & 3) * 2;
    #pragma unroll
    for (int i = 0; i < 4; i++) {
        const int o = o0 + wm * 64 + i * 16 + r;
        const float b0 = bias[o], b1 = bias[o + 8];
        #pragma unroll
        for (int j = 0; j < 4; j++) {
            const int col = l0 + wn * 32 + j * 8 + cb;
            *(float2*)(Xb + (size_t)o * LL + col) =
                make_float2(acc[i][j][0] + b0, acc[i][j][1] + b0);
            *(float2*)(Xb + (size_t)(o + 8) * LL + col) =
                make_float2(acc[i][j][2] + b1, acc[i][j][3] + b1);
        }
    }
}

// ============================================================================
// elementwise split: fp32 -> packed (hi,lo) bf16
// ============================================================================
__global__ __launch_bounds__(256)
void split_k(const float* __restrict__ in, uint32_t* __restrict__ out) {
    const size_t i = ((size_t)blockIdx.x * 256 + threadIdx.x) * 4;
    float4 x = *(const float4*)(in + i);
    uint4 o;
    o.x = splt(x.x); o.y = splt(x.y); o.z = splt(x.z); o.w = splt(x.w);
    *(uint4*)(out + i) = o;
}

// ============================================================================
// Row softmax: read fp32 W, write packed split softmax(W)
// ============================================================================
__global__ __launch_bounds__(256)
void softmax_split() {
    const float* p = g_W + (size_t)blockIdx.x * LL;
    uint32_t* q = g_W2 + (size_t)blockIdx.x * LL;
    const int tid = threadIdx.x;
    float4 v = *(const float4*)(p + tid * 4);

    float m = fmaxf(fmaxf(v.x, v.y), fmaxf(v.z, v.w));
    #pragma unroll
    for (int o = 16; o; o >>= 1) m = fmaxf(m, __shfl_xor_sync(~0u, m, o));
    __shared__ float redm[8], reds[8];
    if ((tid & 31) == 0) redm[tid >> 5] = m;
    __syncthreads();
    float mx = redm[0];
    #pragma unroll
    for (int w = 1; w < 8; w++) mx = fmaxf(mx, redm[w]);

    v.x = expf(v.x - mx); v.y = expf(v.y - mx);
    v.z = expf(v.z - mx); v.w = expf(v.w - mx);
    float s = v.x + v.y + v.z + v.w;
    #pragma unroll
    for (int o = 16; o; o >>= 1) s += __shfl_xor_sync(~0u, s, o);
    if ((tid & 31) == 0) reds[tid >> 5] = s;
    __syncthreads();
    float st = 0.f;
    #pragma unroll
    for (int w = 0; w < 8; w++) st += reds[w];

    float inv = 1.0f / st;
    uint4 o;
    o.x = splt(v.x * inv); o.y = splt(v.y * inv);
    o.z = splt(v.z * inv); o.w = splt(v.w * inv);
    *(uint4*)(q + tid * 4) = o;
}

// ============================================================================
// BN stats + normalize + swish
// ============================================================================
__global__ __launch_bounds__(256)
void bn_stats() {
    const int o = blockIdx.x;
    float s = 0.f, sq = 0.f;
    for (int idx = threadIdx.x; idx < Bb * LL; idx += 256) {
        const int b = idx >> 10, l = idx & (LL - 1);
        float x = g_x[((size_t)b * Cc + o) * LL + l];
        s += x; sq += x * x;
    }
    __shared__ float rs[256], rq[256];
    rs[threadIdx.x] = s; rq[threadIdx.x] = sq;
    __syncthreads();
    for (int st = 128; st; st >>= 1) {
        if (threadIdx.x < st) {
            rs[threadIdx.x] += rs[threadIdx.x + st];
            rq[threadIdx.x] += rq[threadIdx.x + st];
        }
        __syncthreads();
    }
    if (threadIdx.x == 0) {
        const float n = (float)(Bb * LL);
        float mean = rs[0] / n;
        float var  = rq[0] / n - mean * mean;
        g_stats[o] = mean;
        g_stats[Cc + o] = rsqrtf(var + 1e-5f);
    }
}

__global__ __launch_bounds__(256)
void bn_swish(const float* __restrict__ gamma, const float* __restrict__ beta,
              float* __restrict__ out) {
    const size_t i = ((size_t)blockIdx.x * blockDim.x + threadIdx.x) * 4;
    const int o = (int)((i >> 10) & (Cc - 1));
    const float m = g_stats[o], is = g_stats[Cc + o];
    const float ga = gamma[o], be = beta[o];
    float4 x = *(const float4*)(g_x + i);
    float4 y;
    { float xn = (x.x - m) * is * ga + be; y.x = xn / (1.f + expf(-xn)); }
    { float xn = (x.y - m) * is * ga + be; y.y = xn / (1.f + expf(-xn)); }
    { float xn = (x.z - m) * is * ga + be; y.z = xn / (1.f + expf(-xn)); }
    { float xn = (x.w - m) * is * ga + be; y.w = xn / (1.f + expf(-xn)); }
    *(float4*)(out + i) = y;
}

// ============================================================================
// launch
// ============================================================================
extern "C" void kernel_launch(void* const* d_in, const int* in_sizes, int n_in,
                              void* d_out, int out_size) {
    const float* c_in   = (const float*)d_in[0];
    const float* e_in   = (const float*)d_in[1];
    const float* conv_w = (const float*)d_in[2];
    const float* conv_b = (const float*)d_in[3];
    const float* gamma  = (const float*)d_in[4];
    const float* beta   = (const float*)d_in[5];
    float* out = (float*)d_out;

    uint32_t *c2, *e2, *t12, *t22, *cw2;
    cudaGetSymbolAddress((void**)&c2,  g_c2);
    cudaGetSymbolAddress((void**)&e2,  g_e2);
    cudaGetSymbolAddress((void**)&t12, g_t12);
    cudaGetSymbolAddress((void**)&t22, g_t22);
    cudaGetSymbolAddress((void**)&cw2, g_cw2);

    const int NEL = Bb * Cc * LL;   // 4M

    // pre-split inputs
    split_k<<<NEL / 1024, 256>>>(c_in, c2);
    split_k<<<NEL / 1024, 256>>>(e_in, e2);
    split_k<<<Cc * Cc / 1024, 256>>>(conv_w, cw2);

    // attn1: _c = attn(q=e, k=c, v=c)
    qk_bf<<<dim3(8, 8, BH), 256>>>(e2, c2);
    softmax_split<<<BH * LL, 256>>>();
    av_bf<<<dim3(8, 1, BH), 256>>>(c2, t12);

    // attn2: _e = attn(q=_c, k=e, v=e)
    qk_bf<<<dim3(8, 8, BH), 256>>>(t12, e2);
    softmax_split<<<BH * LL, 256>>>();
    av_bf<<<dim3(8, 1, BH), 256>>>(e2, t22);

    // proj: 1x1 conv + bias, then BN + swish
    conv_bf<<<dim3(8, 4, 8), 256>>>(cw2, t22, conv_b);
    bn_stats<<<Cc, 256>>>();
    bn_swish<<<NEL / 1024, 256>>>(gamma, beta, out);
}